// round 12
// baseline (speedup 1.0000x reference)
#include <cuda_runtime.h>
#include <math.h>

#define TWO_PI_F  6.28318530717958647692f
#define TWO_PI2_F 19.739208802178716f   /* 2*pi^2 */

#define NMAX 8192
#define PMAX 64
#define KPAD 520
#define ACH 16             /* k per adjoint chunk (multiple of 4!) */
#define AZ 16              /* adjoint N-splits */
#define AE 8               /* elements per adjoint thread */
#define ABLK 64            /* adjoint block size */
#define PROJ_PTS 128
#define PG 2               /* slices per forward block */
#define FBLK 128           /* forward block size */

typedef unsigned long long u64p;

// ---------- packed f32x2 helpers ----------
__device__ __forceinline__ u64p pk2(float lo, float hi) {
    u64p r; asm("mov.b64 %0, {%1, %2};" : "=l"(r) : "f"(lo), "f"(hi)); return r;
}
__device__ __forceinline__ void upk2(u64p v, float& lo, float& hi) {
    asm("mov.b64 {%0, %1}, %2;" : "=f"(lo), "=f"(hi) : "l"(v));
}
__device__ __forceinline__ u64p fma2(u64p a, u64p b, u64p c) {
    u64p d; asm("fma.rn.f32x2 %0, %1, %2, %3;" : "=l"(d) : "l"(a), "l"(b), "l"(c)); return d;
}

// ---------- device scratch ----------
__device__ float  g_A[PMAX * NMAX];    // sf * <x_n, xi_p>, [p][n]
__device__ float  g_B[PMAX * NMAX];    // sf * <y_m, xi_p>, [p][m]
__device__ float2 g_CS[PMAX * KPAD];   // (C*kft2, S*kft2), slot j = k-1
__device__ float  g_kft2[KPAD];        // 2*kft(h)/P, thresholded
__device__ unsigned int g_norm2max_bits;   // reset by last block each call
__device__ unsigned int g_ctr;             // reset by last block each call
__device__ int    g_hmax;
__device__ int    g_kmin;
__device__ float  g_sf;

// ---------- fused: zero buffers + row-norm max + kft (last-block pattern) ----------
__global__ void __launch_bounds__(256) norm_kft_kernel(
        const float* __restrict__ x, const float* __restrict__ y,
        const float* __restrict__ scale, float* __restrict__ out,
        int N, int M, int d, float dd, int P) {
    __shared__ float wmax[8];
    __shared__ float sred[256];
    __shared__ int s_flag, s_hmax, s_kmin;
    int tid = threadIdx.x;
    int i = blockIdx.x * 256 + tid;
    int stride = gridDim.x * 256;

    float2 z2 = make_float2(0.f, 0.f);
    for (int j = i; j < PMAX * KPAD; j += stride) g_CS[j] = z2;
    for (int j = i; j < M; j += stride) out[j] = 0.f;

    float v = 0.f;
    int T = N + M;
    if (i < T) {
        const float* row = (i < N) ? (x + (size_t)i * d) : (y + (size_t)(i - N) * d);
        float s = 0.f;
        for (int j = 0; j < d; j += 4) {
            float4 q = *reinterpret_cast<const float4*>(row + j);
            s = fmaf(q.x, q.x, s); s = fmaf(q.y, q.y, s);
            s = fmaf(q.z, q.z, s); s = fmaf(q.w, q.w, s);
        }
        v = s;
    }
#pragma unroll
    for (int off = 16; off > 0; off >>= 1)
        v = fmaxf(v, __shfl_xor_sync(0xffffffffu, v, off));
    if ((tid & 31) == 0) wmax[tid >> 5] = v;
    __syncthreads();
    if (tid == 0) {
        float m = wmax[0];
#pragma unroll
        for (int wq = 1; wq < 8; wq++) m = fmaxf(m, wmax[wq]);
        if (m > 0.f) atomicMax(&g_norm2max_bits, __float_as_uint(m));
        __threadfence();
        unsigned int prev = atomicAdd(&g_ctr, 1u);
        s_flag = (prev == gridDim.x - 1) ? 1 : 0;
    }
    __syncthreads();
    if (!s_flag) return;

    __threadfence();
    unsigned int nb_bits = atomicAdd(&g_norm2max_bits, 0u);
    float nm = sqrtf(__uint_as_float(nb_bits));
    float sf = 0.3f / nm;
    float sr = scale[0] * sf;
    float s2 = sr * sr;
    float base = 0.5f * dd * __logf(TWO_PI2_F * s2) - lgammaf(0.5f * dd);

    int h1 = tid + 1;
    int h2 = tid + 257;
    float k1 = 0.f, k2 = 0.f;
    {
        float hp = (float)h1;
        float lv = base + (dd - 1.f) * __logf(hp) - TWO_PI2_F * s2 * hp * hp;
        k1 = __expf(lv);
    }
    if (h2 <= 511) {
        float hp = (float)h2;
        float lv = base + (dd - 1.f) * __logf(hp) - TWO_PI2_F * s2 * hp * hp;
        k2 = __expf(lv);
    }
    sred[tid] = fmaxf(k1, k2);
    if (tid == 0) { s_hmax = 0; s_kmin = 0x7fffffff; }
    __syncthreads();
    for (int s = 128; s > 0; s >>= 1) {
        if (tid < s) sred[tid] = fmaxf(sred[tid], sred[tid + s]);
        __syncthreads();
    }
    float maxv = sred[0];
    float thr = maxv * 1e-5f;
    float fscale = 2.f / (float)P;

    bool keep1 = (maxv > 0.f) && (k1 > thr);
    g_kft2[h1] = keep1 ? k1 * fscale : 0.f;
    if (keep1) { atomicMax(&s_hmax, h1); atomicMin(&s_kmin, h1); }
    if (h2 <= 511) {
        bool keep2 = (maxv > 0.f) && (k2 > thr);
        g_kft2[h2] = keep2 ? k2 * fscale : 0.f;
        if (keep2) { atomicMax(&s_hmax, h2); atomicMin(&s_kmin, h2); }
    }
    __syncthreads();
    if (tid == 0) {
        g_kft2[0] = 0.f;
        g_hmax = s_hmax;
        g_kmin = s_kmin;
        g_sf = sf;
        g_ctr = 0u;
        g_norm2max_bits = 0u;
    }
}

// ---------- proj5: smem-staged, P split in halves across blockIdx.z ----------
__global__ void __launch_bounds__(256) proj5_kernel(const float* __restrict__ xpts,
                                                    const float* __restrict__ ypts,
                                                    const float* __restrict__ xis,
                                                    int N, int M, int P) {
    __shared__ float xi_t[64 * 34];
    __shared__ float pts_s[PROJ_PTS * 68];
    int tid = threadIdx.x;
    int which = blockIdx.y;
    int pbase = blockIdx.z * 32;
    const float* pts = which ? ypts : xpts;
    int npts = which ? M : N;
    int base = blockIdx.x * PROJ_PTS;

    for (int idx = tid; idx < 32 * 64; idx += 256) {
        int pl = idx >> 6, dc = idx & 63;
        int pg = pbase + pl;
        xi_t[dc * 34 + pl] = (pg < P) ? xis[(size_t)pg * 64 + dc] : 0.f;
    }
    for (int idx = tid; idx < PROJ_PTS * 16; idx += 256) {
        int r = idx >> 4, j4 = idx & 15;
        int n = base + r;
        float4 v = make_float4(0.f, 0.f, 0.f, 0.f);
        if (n < npts) v = *reinterpret_cast<const float4*>(pts + (size_t)n * 64 + j4 * 4);
        *reinterpret_cast<float4*>(pts_s + r * 68 + j4 * 4) = v;
    }
    __syncthreads();

    int slot = tid & 63;
    int g = tid >> 6;
    const float4* r0 = reinterpret_cast<const float4*>(pts_s + slot * 68);
    const float4* r1 = reinterpret_cast<const float4*>(pts_s + (slot + 64) * 68);

    u64p acc0[4], acc1[4];
#pragma unroll
    for (int q = 0; q < 4; q++) { acc0[q] = 0ull; acc1[q] = 0ull; }

#pragma unroll
    for (int j4 = 0; j4 < 16; j4++) {
        float4 v0 = r0[j4];
        float4 v1 = r1[j4];
#pragma unroll
        for (int s = 0; s < 4; s++) {
            float f0 = (s == 0) ? v0.x : (s == 1) ? v0.y : (s == 2) ? v0.z : v0.w;
            float f1 = (s == 0) ? v1.x : (s == 1) ? v1.y : (s == 2) ? v1.z : v1.w;
            u64p vv0 = pk2(f0, f0);
            u64p vv1 = pk2(f1, f1);
            const float* xb = xi_t + (j4 * 4 + s) * 34 + g * 8;
#pragma unroll
            for (int q = 0; q < 4; q++) {
                u64p xq = *reinterpret_cast<const u64p*>(xb + 2 * q);
                acc0[q] = fma2(vv0, xq, acc0[q]);
                acc1[q] = fma2(vv1, xq, acc1[q]);
            }
        }
    }

    float sf = g_sf;
    float* dst = which ? g_B : g_A;
    int n0 = base + slot, n1 = n0 + 64;
#pragma unroll
    for (int q = 0; q < 4; q++) {
        float a, b, c, dq;
        upk2(acc0[q], a, b);
        upk2(acc1[q], c, dq);
        int p0 = pbase + g * 8 + 2 * q;
        if (p0 < P) {
            if (n0 < npts) dst[(size_t)p0 * npts + n0] = a * sf;
            if (n1 < npts) dst[(size_t)p0 * npts + n1] = c * sf;
        }
        if (p0 + 1 < P) {
            if (n0 < npts) dst[(size_t)(p0 + 1) * npts + n0] = b * sf;
            if (n1 < npts) dst[(size_t)(p0 + 1) * npts + n1] = dq * sf;
        }
    }
}

// ---------- adjoint: chunk-carried Chebyshev + warp reduce-scatter, AE=8, block=64 ----------
__global__ void __launch_bounds__(ABLK) adjoint_kernel(const float* __restrict__ w, int N) {
    int p = blockIdx.x;
    int z = blockIdx.y;
    int hmax = g_hmax;
    if (hmax < 1) return;
    int klo = g_kmin; if (klo < 1) klo = 1;
    int nchunk = (hmax - klo + ACH) / ACH;

    int tid = threadIdx.x;
    int lane = tid & 31;
    const float* arow = g_A + (size_t)p * N;
    int seg = (N + AZ - 1) / AZ;
    int st = z * seg;
    int en = st + seg; if (en > N) en = N;

    float fklo = (float)klo;
    u64p vc[AE], vp[AE], t2p[AE], nt2p[AE], wp[AE];
#pragma unroll
    for (int e = 0; e < AE; e++) {
        int n = st + tid + e * ABLK;
        bool ok = (n < en);
        float a  = ok ? arow[n] : 0.f;
        float ww = ok ? w[n]    : 0.f;
        float us, uc;
        __sincosf(TWO_PI_F * a, &us, &uc);
        float t = fklo * a;
        float er = fmaf(fklo, a, -t);
        float f = (t - rintf(t)) + er;
        float zs, zc;
        __sincosf(TWO_PI_F * f, &zs, &zc);
        float zmc = fmaf(zc, uc,  zs * us);
        float zms = fmaf(zs, uc, -zc * us);
        vc[e] = pk2(zc, zs);
        vp[e] = pk2(-zmc, -zms);
        t2p[e]  = pk2( 2.f * uc,  2.f * uc);
        nt2p[e] = pk2(-2.f * uc, -2.f * uc);
        wp[e] = pk2(ww, ww);
    }

    for (int c = 0; c < nchunk; c++) {
        int k0 = klo + c * ACH;
        u64p accv[ACH];
#pragma unroll
        for (int j = 0; j < ACH; j++) accv[j] = 0ull;

#pragma unroll
        for (int j = 0; j < ACH; j++) {
#pragma unroll
            for (int e = 0; e < AE; e++) {
                accv[j] = fma2(wp[e], vc[e], accv[j]);
                u64p vn = fma2((j & 1) ? nt2p[e] : t2p[e], vc[e], vp[e]);
                vp[e] = vc[e]; vc[e] = vn;
            }
        }

        float a[2 * ACH];
#pragma unroll
        for (int j = 0; j < ACH; j++) upk2(accv[j], a[2 * j], a[2 * j + 1]);

#pragma unroll
        for (int B = 16; B >= 1; B >>= 1) {
            bool bit = (lane & B) != 0;
#pragma unroll
            for (int i = 0; i < B; i++) {
                float snd = bit ? a[i] : a[i + B];
                float kp  = bit ? a[i + B] : a[i];
                a[i] = kp + __shfl_xor_sync(0xffffffffu, snd, B);
            }
        }

        int j = lane >> 1;
        int k = k0 + j;
        float sg = ((j & 2) == 0) ? 1.f : -1.f;
        if (k <= 511) {
            float fkt = g_kft2[k];
            if (fkt != 0.f)
                atomicAdd(reinterpret_cast<float*>(g_CS + (size_t)p * KPAD + (k - 1)) + (lane & 1),
                          a[0] * (sg * fkt));
        }
    }
}

// ---------- forward helpers ----------
__device__ __forceinline__ void clenshaw_step(u64p& b1, u64p& b2, u64p t2, u64p negv, u64p coef) {
    u64p t = fma2(t2, b1, coef);
    u64p n = fma2(negv, b2, t);
    b2 = b1; b1 = n;
}
__device__ __forceinline__ float clenshaw_fin(u64p b1, u64p b2, float fk0,
                                              float bv, float cu, float su) {
    float t = fk0 * bv;
    float e = fmaf(fk0, bv, -t);
    float f = (t - rintf(t)) + e;
    float sK, cK;
    __sincosf(TWO_PI_F * f, &sK, &cK);
    float cKm = fmaf(cK, cu,  sK * su);
    float sKm = fmaf(sK, cu, -cK * su);
    float b1l, b1h, b2l, b2h;
    upk2(b1, b1l, b1h); upk2(b2, b2l, b2h);
    return fmaf(b1l, cK, -b2l * cKm) + fmaf(b1h, sK, -b2h * sKm);
}

// ---------- forward: MV=2 split-range Clenshaw, software-pipelined loads ----------
__global__ void __launch_bounds__(FBLK) forward_kernel(float* __restrict__ out,
                                                       int M, int P) {
    int hmax = g_hmax;
    if (hmax < 1) return;
    int kmin = g_kmin; if (kmin < 1) kmin = 1;
    int KE  = ((hmax + 1) >> 1) << 1;
    int jlo = ((kmin - 1) >> 1) << 1;
    int T = (KE - jlo) >> 1;        // coefficient pairs
    int L = (T + 1) >> 1;           // iters per half (upper padded into zero slots)
    int idx0 = jlo >> 1;
    float fklo = (float)(jlo + 1);
    float fkhi = (float)(jlo + 2 * L + 1);
    const u64p negv = pk2(-1.f, -1.f);

    int Mh = (M + 1) >> 1;
    int i = blockIdx.x * FBLK + threadIdx.x;
    if (i >= Mh) return;
    int m0 = i, m1 = i + Mh;
    bool has1 = (m1 < M);
    int p0 = blockIdx.y * PG;

    if (p0 + 1 < P) {
        float ba0 = g_B[(size_t)p0 * M + m0];
        float bb0 = g_B[(size_t)(p0 + 1) * M + m0];
        float ba1 = has1 ? g_B[(size_t)p0 * M + m1] : 0.f;
        float bb1 = has1 ? g_B[(size_t)(p0 + 1) * M + m1] : 0.f;
        float sa0, ca0, sb0, cb0, sa1, ca1, sb1, cb1;
        __sincosf(TWO_PI_F * ba0, &sa0, &ca0);
        __sincosf(TWO_PI_F * bb0, &sb0, &cb0);
        __sincosf(TWO_PI_F * ba1, &sa1, &ca1);
        __sincosf(TWO_PI_F * bb1, &sb1, &cb1);
        u64p t2a0 = pk2(2.f * ca0, 2.f * ca0);
        u64p t2b0 = pk2(2.f * cb0, 2.f * cb0);
        u64p t2a1 = pk2(2.f * ca1, 2.f * ca1);
        u64p t2b1 = pk2(2.f * cb1, 2.f * cb1);
        u64p c1[8], c2[8];
#pragma unroll
        for (int q = 0; q < 8; q++) { c1[q] = 0ull; c2[q] = 0ull; }
        const ulonglong2* CA = reinterpret_cast<const ulonglong2*>(g_CS + (size_t)p0 * KPAD);
        const ulonglong2* CB = reinterpret_cast<const ulonglong2*>(g_CS + (size_t)(p0 + 1) * KPAD);
        // software pipeline: prefetch next iteration's 4 coefficient vectors
        ulonglong2 fa  = __ldg(CA + idx0 + (L - 1));
        ulonglong2 fah = __ldg(CA + idx0 + L + (L - 1));
        ulonglong2 fb  = __ldg(CB + idx0 + (L - 1));
        ulonglong2 fbh = __ldg(CB + idx0 + L + (L - 1));
        for (int it = L - 1; it >= 0; it--) {
            int nx = (it > 0) ? (it - 1) : 0;   // clamped: always-valid prefetch
            ulonglong2 pa  = __ldg(CA + idx0 + nx);
            ulonglong2 pah = __ldg(CA + idx0 + L + nx);
            ulonglong2 pb  = __ldg(CB + idx0 + nx);
            ulonglong2 pbh = __ldg(CB + idx0 + L + nx);
            clenshaw_step(c1[0], c2[0], t2a0, negv, fa.y);
            clenshaw_step(c1[1], c2[1], t2a0, negv, fah.y);
            clenshaw_step(c1[2], c2[2], t2b0, negv, fb.y);
            clenshaw_step(c1[3], c2[3], t2b0, negv, fbh.y);
            clenshaw_step(c1[4], c2[4], t2a1, negv, fa.y);
            clenshaw_step(c1[5], c2[5], t2a1, negv, fah.y);
            clenshaw_step(c1[6], c2[6], t2b1, negv, fb.y);
            clenshaw_step(c1[7], c2[7], t2b1, negv, fbh.y);
            clenshaw_step(c1[0], c2[0], t2a0, negv, fa.x);
            clenshaw_step(c1[1], c2[1], t2a0, negv, fah.x);
            clenshaw_step(c1[2], c2[2], t2b0, negv, fb.x);
            clenshaw_step(c1[3], c2[3], t2b0, negv, fbh.x);
            clenshaw_step(c1[4], c2[4], t2a1, negv, fa.x);
            clenshaw_step(c1[5], c2[5], t2a1, negv, fah.x);
            clenshaw_step(c1[6], c2[6], t2b1, negv, fb.x);
            clenshaw_step(c1[7], c2[7], t2b1, negv, fbh.x);
            fa = pa; fah = pah; fb = pb; fbh = pbh;
        }
        float tot0 = clenshaw_fin(c1[0], c2[0], fklo, ba0, ca0, sa0)
                   + clenshaw_fin(c1[1], c2[1], fkhi, ba0, ca0, sa0)
                   + clenshaw_fin(c1[2], c2[2], fklo, bb0, cb0, sb0)
                   + clenshaw_fin(c1[3], c2[3], fkhi, bb0, cb0, sb0);
        atomicAdd(out + m0, tot0);
        if (has1) {
            float tot1 = clenshaw_fin(c1[4], c2[4], fklo, ba1, ca1, sa1)
                       + clenshaw_fin(c1[5], c2[5], fkhi, ba1, ca1, sa1)
                       + clenshaw_fin(c1[6], c2[6], fklo, bb1, cb1, sb1)
                       + clenshaw_fin(c1[7], c2[7], fkhi, bb1, cb1, sb1);
            atomicAdd(out + m1, tot1);
        }
    } else if (p0 < P) {   // odd-P tail: single slice, two m
        float ba0 = g_B[(size_t)p0 * M + m0];
        float ba1 = has1 ? g_B[(size_t)p0 * M + m1] : 0.f;
        float sa0, ca0, sa1, ca1;
        __sincosf(TWO_PI_F * ba0, &sa0, &ca0);
        __sincosf(TWO_PI_F * ba1, &sa1, &ca1);
        u64p t2a0 = pk2(2.f * ca0, 2.f * ca0);
        u64p t2a1 = pk2(2.f * ca1, 2.f * ca1);
        u64p c1[4], c2[4];
#pragma unroll
        for (int q = 0; q < 4; q++) { c1[q] = 0ull; c2[q] = 0ull; }
        const ulonglong2* CA = reinterpret_cast<const ulonglong2*>(g_CS + (size_t)p0 * KPAD);
        ulonglong2 fa  = __ldg(CA + idx0 + (L - 1));
        ulonglong2 fah = __ldg(CA + idx0 + L + (L - 1));
        for (int it = L - 1; it >= 0; it--) {
            int nx = (it > 0) ? (it - 1) : 0;
            ulonglong2 pa  = __ldg(CA + idx0 + nx);
            ulonglong2 pah = __ldg(CA + idx0 + L + nx);
            clenshaw_step(c1[0], c2[0], t2a0, negv, fa.y);
            clenshaw_step(c1[1], c2[1], t2a0, negv, fah.y);
            clenshaw_step(c1[2], c2[2], t2a1, negv, fa.y);
            clenshaw_step(c1[3], c2[3], t2a1, negv, fah.y);
            clenshaw_step(c1[0], c2[0], t2a0, negv, fa.x);
            clenshaw_step(c1[1], c2[1], t2a0, negv, fah.x);
            clenshaw_step(c1[2], c2[2], t2a1, negv, fa.x);
            clenshaw_step(c1[3], c2[3], t2a1, negv, fah.x);
            fa = pa; fah = pah;
        }
        float tot0 = clenshaw_fin(c1[0], c2[0], fklo, ba0, ca0, sa0)
                   + clenshaw_fin(c1[1], c2[1], fkhi, ba0, ca0, sa0);
        atomicAdd(out + m0, tot0);
        if (has1) {
            float tot1 = clenshaw_fin(c1[2], c2[2], fklo, ba1, ca1, sa1)
                       + clenshaw_fin(c1[3], c2[3], fkhi, ba1, ca1, sa1);
            atomicAdd(out + m1, tot1);
        }
    }
}

extern "C" void kernel_launch(void* const* d_in, const int* in_sizes, int n_in,
                              void* d_out, int out_size) {
    const float* x     = (const float*)d_in[0];
    const float* y     = (const float*)d_in[1];
    const float* w     = (const float*)d_in[2];
    const float* scale = (const float*)d_in[3];
    const float* xis   = (const float*)d_in[4];
    float* out = (float*)d_out;

    int N = in_sizes[2];
    int d = in_sizes[0] / N;
    int M = out_size;
    int P = in_sizes[4] / d;

    int nb = (N + M + 255) / 256;
    norm_kft_kernel<<<nb, 256>>>(x, y, scale, out, N, M, d, (float)d, P);
    int nmax = (N > M) ? N : M;
    dim3 pgrid((nmax + PROJ_PTS - 1) / PROJ_PTS, 2, 2);
    proj5_kernel<<<pgrid, 256>>>(x, y, xis, N, M, P);
    adjoint_kernel<<<dim3(P, AZ), ABLK>>>(w, N);
    int Mh = (M + 1) / 2;
    int ngroups = (P + PG - 1) / PG;
    forward_kernel<<<dim3((Mh + FBLK - 1) / FBLK, ngroups), FBLK>>>(out, M, P);
}

// round 13
// speedup vs baseline: 1.0449x; 1.0449x over previous
#include <cuda_runtime.h>
#include <math.h>

#define TWO_PI_F  6.28318530717958647692f
#define TWO_PI2_F 19.739208802178716f   /* 2*pi^2 */

#define NMAX 8192
#define PMAX 64
#define KPAD 520
#define ACH 16             /* k per adjoint chunk (multiple of 4!) */
#define AZ 16              /* adjoint N-splits */
#define AE 8               /* elements per adjoint thread */
#define ABLK 64            /* adjoint block size */
#define PROJ_PTS 128
#define PG 2               /* slices per forward block */
#define FBLK 128           /* forward block size */

typedef unsigned long long u64p;

// ---------- packed f32x2 helpers ----------
__device__ __forceinline__ u64p pk2(float lo, float hi) {
    u64p r; asm("mov.b64 %0, {%1, %2};" : "=l"(r) : "f"(lo), "f"(hi)); return r;
}
__device__ __forceinline__ void upk2(u64p v, float& lo, float& hi) {
    asm("mov.b64 {%0, %1}, %2;" : "=f"(lo), "=f"(hi) : "l"(v));
}
__device__ __forceinline__ u64p fma2(u64p a, u64p b, u64p c) {
    u64p d; asm("fma.rn.f32x2 %0, %1, %2, %3;" : "=l"(d) : "l"(a), "l"(b), "l"(c)); return d;
}

// ---------- device scratch ----------
__device__ float  g_A[PMAX * NMAX];    // sf * <x_n, xi_p>, [p][n]
__device__ float  g_B[PMAX * NMAX];    // sf * <y_m, xi_p>, [p][m]
__device__ float2 g_CS[PMAX * KPAD];   // (C*kft2, S*kft2), slot j = k-1
__device__ float  g_kft2[KPAD];        // 2*kft(h)/P, thresholded
__device__ unsigned int g_norm2max_bits;   // reset by last block each call
__device__ unsigned int g_ctr;             // reset by last block each call
__device__ int    g_hmax;
__device__ int    g_kmin;
__device__ float  g_sf;

// ---------- fused: zero buffers + row-norm max + kft (last-block pattern) ----------
__global__ void __launch_bounds__(256) norm_kft_kernel(
        const float* __restrict__ x, const float* __restrict__ y,
        const float* __restrict__ scale, float* __restrict__ out,
        int N, int M, int d, float dd, int P) {
    __shared__ float wmax[8];
    __shared__ float sred[256];
    __shared__ int s_flag, s_hmax, s_kmin;
    int tid = threadIdx.x;
    int i = blockIdx.x * 256 + tid;
    int stride = gridDim.x * 256;

    float2 z2 = make_float2(0.f, 0.f);
    for (int j = i; j < PMAX * KPAD; j += stride) g_CS[j] = z2;
    for (int j = i; j < M; j += stride) out[j] = 0.f;

    float v = 0.f;
    int T = N + M;
    if (i < T) {
        const float* row = (i < N) ? (x + (size_t)i * d) : (y + (size_t)(i - N) * d);
        float s = 0.f;
        for (int j = 0; j < d; j += 4) {
            float4 q = *reinterpret_cast<const float4*>(row + j);
            s = fmaf(q.x, q.x, s); s = fmaf(q.y, q.y, s);
            s = fmaf(q.z, q.z, s); s = fmaf(q.w, q.w, s);
        }
        v = s;
    }
#pragma unroll
    for (int off = 16; off > 0; off >>= 1)
        v = fmaxf(v, __shfl_xor_sync(0xffffffffu, v, off));
    if ((tid & 31) == 0) wmax[tid >> 5] = v;
    __syncthreads();
    if (tid == 0) {
        float m = wmax[0];
#pragma unroll
        for (int wq = 1; wq < 8; wq++) m = fmaxf(m, wmax[wq]);
        if (m > 0.f) atomicMax(&g_norm2max_bits, __float_as_uint(m));
        __threadfence();
        unsigned int prev = atomicAdd(&g_ctr, 1u);
        s_flag = (prev == gridDim.x - 1) ? 1 : 0;
    }
    __syncthreads();
    if (!s_flag) return;

    __threadfence();
    unsigned int nb_bits = atomicAdd(&g_norm2max_bits, 0u);
    float nm = sqrtf(__uint_as_float(nb_bits));
    float sf = 0.3f / nm;
    float sr = scale[0] * sf;
    float s2 = sr * sr;
    float base = 0.5f * dd * __logf(TWO_PI2_F * s2) - lgammaf(0.5f * dd);

    int h1 = tid + 1;
    int h2 = tid + 257;
    float k1 = 0.f, k2 = 0.f;
    {
        float hp = (float)h1;
        float lv = base + (dd - 1.f) * __logf(hp) - TWO_PI2_F * s2 * hp * hp;
        k1 = __expf(lv);
    }
    if (h2 <= 511) {
        float hp = (float)h2;
        float lv = base + (dd - 1.f) * __logf(hp) - TWO_PI2_F * s2 * hp * hp;
        k2 = __expf(lv);
    }
    sred[tid] = fmaxf(k1, k2);
    if (tid == 0) { s_hmax = 0; s_kmin = 0x7fffffff; }
    __syncthreads();
    for (int s = 128; s > 0; s >>= 1) {
        if (tid < s) sred[tid] = fmaxf(sred[tid], sred[tid + s]);
        __syncthreads();
    }
    float maxv = sred[0];
    float thr = maxv * 1e-5f;
    float fscale = 2.f / (float)P;

    bool keep1 = (maxv > 0.f) && (k1 > thr);
    g_kft2[h1] = keep1 ? k1 * fscale : 0.f;
    if (keep1) { atomicMax(&s_hmax, h1); atomicMin(&s_kmin, h1); }
    if (h2 <= 511) {
        bool keep2 = (maxv > 0.f) && (k2 > thr);
        g_kft2[h2] = keep2 ? k2 * fscale : 0.f;
        if (keep2) { atomicMax(&s_hmax, h2); atomicMin(&s_kmin, h2); }
    }
    __syncthreads();
    if (tid == 0) {
        g_kft2[0] = 0.f;
        g_hmax = s_hmax;
        g_kmin = s_kmin;
        g_sf = sf;
        g_ctr = 0u;
        g_norm2max_bits = 0u;
    }
}

// ---------- proj5: smem-staged, P split in halves across blockIdx.z ----------
__global__ void __launch_bounds__(256) proj5_kernel(const float* __restrict__ xpts,
                                                    const float* __restrict__ ypts,
                                                    const float* __restrict__ xis,
                                                    int N, int M, int P) {
    __shared__ float xi_t[64 * 34];
    __shared__ float pts_s[PROJ_PTS * 68];
    int tid = threadIdx.x;
    int which = blockIdx.y;
    int pbase = blockIdx.z * 32;
    const float* pts = which ? ypts : xpts;
    int npts = which ? M : N;
    int base = blockIdx.x * PROJ_PTS;

    for (int idx = tid; idx < 32 * 64; idx += 256) {
        int pl = idx >> 6, dc = idx & 63;
        int pg = pbase + pl;
        xi_t[dc * 34 + pl] = (pg < P) ? xis[(size_t)pg * 64 + dc] : 0.f;
    }
    for (int idx = tid; idx < PROJ_PTS * 16; idx += 256) {
        int r = idx >> 4, j4 = idx & 15;
        int n = base + r;
        float4 v = make_float4(0.f, 0.f, 0.f, 0.f);
        if (n < npts) v = *reinterpret_cast<const float4*>(pts + (size_t)n * 64 + j4 * 4);
        *reinterpret_cast<float4*>(pts_s + r * 68 + j4 * 4) = v;
    }
    __syncthreads();

    int slot = tid & 63;
    int g = tid >> 6;
    const float4* r0 = reinterpret_cast<const float4*>(pts_s + slot * 68);
    const float4* r1 = reinterpret_cast<const float4*>(pts_s + (slot + 64) * 68);

    u64p acc0[4], acc1[4];
#pragma unroll
    for (int q = 0; q < 4; q++) { acc0[q] = 0ull; acc1[q] = 0ull; }

#pragma unroll
    for (int j4 = 0; j4 < 16; j4++) {
        float4 v0 = r0[j4];
        float4 v1 = r1[j4];
#pragma unroll
        for (int s = 0; s < 4; s++) {
            float f0 = (s == 0) ? v0.x : (s == 1) ? v0.y : (s == 2) ? v0.z : v0.w;
            float f1 = (s == 0) ? v1.x : (s == 1) ? v1.y : (s == 2) ? v1.z : v1.w;
            u64p vv0 = pk2(f0, f0);
            u64p vv1 = pk2(f1, f1);
            const float* xb = xi_t + (j4 * 4 + s) * 34 + g * 8;
#pragma unroll
            for (int q = 0; q < 4; q++) {
                u64p xq = *reinterpret_cast<const u64p*>(xb + 2 * q);
                acc0[q] = fma2(vv0, xq, acc0[q]);
                acc1[q] = fma2(vv1, xq, acc1[q]);
            }
        }
    }

    float sf = g_sf;
    float* dst = which ? g_B : g_A;
    int n0 = base + slot, n1 = n0 + 64;
#pragma unroll
    for (int q = 0; q < 4; q++) {
        float a, b, c, dq;
        upk2(acc0[q], a, b);
        upk2(acc1[q], c, dq);
        int p0 = pbase + g * 8 + 2 * q;
        if (p0 < P) {
            if (n0 < npts) dst[(size_t)p0 * npts + n0] = a * sf;
            if (n1 < npts) dst[(size_t)p0 * npts + n1] = c * sf;
        }
        if (p0 + 1 < P) {
            if (n0 < npts) dst[(size_t)(p0 + 1) * npts + n0] = b * sf;
            if (n1 < npts) dst[(size_t)(p0 + 1) * npts + n1] = dq * sf;
        }
    }
}

// ---------- adjoint: chunk-carried Chebyshev + warp reduce-scatter, AE=8, block=64 ----------
__global__ void __launch_bounds__(ABLK) adjoint_kernel(const float* __restrict__ w, int N) {
    int p = blockIdx.x;
    int z = blockIdx.y;
    int hmax = g_hmax;
    if (hmax < 1) return;
    int klo = g_kmin; if (klo < 1) klo = 1;
    int nchunk = (hmax - klo + ACH) / ACH;

    int tid = threadIdx.x;
    int lane = tid & 31;
    const float* arow = g_A + (size_t)p * N;
    int seg = (N + AZ - 1) / AZ;
    int st = z * seg;
    int en = st + seg; if (en > N) en = N;

    float fklo = (float)klo;
    u64p vc[AE], vp[AE], t2p[AE], nt2p[AE], wp[AE];
#pragma unroll
    for (int e = 0; e < AE; e++) {
        int n = st + tid + e * ABLK;
        bool ok = (n < en);
        float a  = ok ? arow[n] : 0.f;
        float ww = ok ? w[n]    : 0.f;
        float us, uc;
        __sincosf(TWO_PI_F * a, &us, &uc);
        float t = fklo * a;
        float er = fmaf(fklo, a, -t);
        float f = (t - rintf(t)) + er;
        float zs, zc;
        __sincosf(TWO_PI_F * f, &zs, &zc);
        float zmc = fmaf(zc, uc,  zs * us);
        float zms = fmaf(zs, uc, -zc * us);
        vc[e] = pk2(zc, zs);
        vp[e] = pk2(-zmc, -zms);
        t2p[e]  = pk2( 2.f * uc,  2.f * uc);
        nt2p[e] = pk2(-2.f * uc, -2.f * uc);
        wp[e] = pk2(ww, ww);
    }

    for (int c = 0; c < nchunk; c++) {
        int k0 = klo + c * ACH;
        u64p accv[ACH];
#pragma unroll
        for (int j = 0; j < ACH; j++) accv[j] = 0ull;

#pragma unroll
        for (int j = 0; j < ACH; j++) {
#pragma unroll
            for (int e = 0; e < AE; e++) {
                accv[j] = fma2(wp[e], vc[e], accv[j]);
                u64p vn = fma2((j & 1) ? nt2p[e] : t2p[e], vc[e], vp[e]);
                vp[e] = vc[e]; vc[e] = vn;
            }
        }

        float a[2 * ACH];
#pragma unroll
        for (int j = 0; j < ACH; j++) upk2(accv[j], a[2 * j], a[2 * j + 1]);

#pragma unroll
        for (int B = 16; B >= 1; B >>= 1) {
            bool bit = (lane & B) != 0;
#pragma unroll
            for (int i = 0; i < B; i++) {
                float snd = bit ? a[i] : a[i + B];
                float kp  = bit ? a[i + B] : a[i];
                a[i] = kp + __shfl_xor_sync(0xffffffffu, snd, B);
            }
        }

        int j = lane >> 1;
        int k = k0 + j;
        float sg = ((j & 2) == 0) ? 1.f : -1.f;
        if (k <= 511) {
            float fkt = g_kft2[k];
            if (fkt != 0.f)
                atomicAdd(reinterpret_cast<float*>(g_CS + (size_t)p * KPAD + (k - 1)) + (lane & 1),
                          a[0] * (sg * fkt));
        }
    }
}

// ---------- forward helpers ----------
__device__ __forceinline__ void clenshaw_step(u64p& b1, u64p& b2, u64p t2, u64p negv, u64p coef) {
    u64p t = fma2(t2, b1, coef);
    u64p n = fma2(negv, b2, t);
    b2 = b1; b1 = n;
}
__device__ __forceinline__ float clenshaw_fin(u64p b1, u64p b2, float fk0,
                                              float bv, float cu, float su) {
    float t = fk0 * bv;
    float e = fmaf(fk0, bv, -t);
    float f = (t - rintf(t)) + e;
    float sK, cK;
    __sincosf(TWO_PI_F * f, &sK, &cK);
    float cKm = fmaf(cK, cu,  sK * su);
    float sKm = fmaf(sK, cu, -cK * su);
    float b1l, b1h, b2l, b2h;
    upk2(b1, b1l, b1h); upk2(b2, b2l, b2h);
    return fmaf(b1l, cK, -b2l * cKm) + fmaf(b1h, sK, -b2h * sKm);
}

// ---------- forward: MV=2 split-range Clenshaw (round-10 body, no prefetch) ----------
__global__ void __launch_bounds__(FBLK) forward_kernel(float* __restrict__ out,
                                                       int M, int P) {
    int hmax = g_hmax;
    if (hmax < 1) return;
    int kmin = g_kmin; if (kmin < 1) kmin = 1;
    int KE  = ((hmax + 1) >> 1) << 1;
    int jlo = ((kmin - 1) >> 1) << 1;
    int T = (KE - jlo) >> 1;        // coefficient pairs
    int L = (T + 1) >> 1;           // iters per half (upper padded into zero slots)
    int idx0 = jlo >> 1;
    float fklo = (float)(jlo + 1);
    float fkhi = (float)(jlo + 2 * L + 1);
    const u64p negv = pk2(-1.f, -1.f);

    int Mh = (M + 1) >> 1;
    int i = blockIdx.x * FBLK + threadIdx.x;
    if (i >= Mh) return;
    int m0 = i, m1 = i + Mh;
    bool has1 = (m1 < M);
    int p0 = blockIdx.y * PG;

    if (p0 + 1 < P) {
        float ba0 = g_B[(size_t)p0 * M + m0];
        float bb0 = g_B[(size_t)(p0 + 1) * M + m0];
        float ba1 = has1 ? g_B[(size_t)p0 * M + m1] : 0.f;
        float bb1 = has1 ? g_B[(size_t)(p0 + 1) * M + m1] : 0.f;
        float sa0, ca0, sb0, cb0, sa1, ca1, sb1, cb1;
        __sincosf(TWO_PI_F * ba0, &sa0, &ca0);
        __sincosf(TWO_PI_F * bb0, &sb0, &cb0);
        __sincosf(TWO_PI_F * ba1, &sa1, &ca1);
        __sincosf(TWO_PI_F * bb1, &sb1, &cb1);
        u64p t2a0 = pk2(2.f * ca0, 2.f * ca0);
        u64p t2b0 = pk2(2.f * cb0, 2.f * cb0);
        u64p t2a1 = pk2(2.f * ca1, 2.f * ca1);
        u64p t2b1 = pk2(2.f * cb1, 2.f * cb1);
        u64p c1[8], c2[8];
#pragma unroll
        for (int q = 0; q < 8; q++) { c1[q] = 0ull; c2[q] = 0ull; }
        const ulonglong2* CA = reinterpret_cast<const ulonglong2*>(g_CS + (size_t)p0 * KPAD);
        const ulonglong2* CB = reinterpret_cast<const ulonglong2*>(g_CS + (size_t)(p0 + 1) * KPAD);
        for (int it = L - 1; it >= 0; it--) {
            ulonglong2 fa  = __ldg(CA + idx0 + it);
            ulonglong2 fah = __ldg(CA + idx0 + L + it);
            ulonglong2 fb  = __ldg(CB + idx0 + it);
            ulonglong2 fbh = __ldg(CB + idx0 + L + it);
            clenshaw_step(c1[0], c2[0], t2a0, negv, fa.y);
            clenshaw_step(c1[1], c2[1], t2a0, negv, fah.y);
            clenshaw_step(c1[2], c2[2], t2b0, negv, fb.y);
            clenshaw_step(c1[3], c2[3], t2b0, negv, fbh.y);
            clenshaw_step(c1[4], c2[4], t2a1, negv, fa.y);
            clenshaw_step(c1[5], c2[5], t2a1, negv, fah.y);
            clenshaw_step(c1[6], c2[6], t2b1, negv, fb.y);
            clenshaw_step(c1[7], c2[7], t2b1, negv, fbh.y);
            clenshaw_step(c1[0], c2[0], t2a0, negv, fa.x);
            clenshaw_step(c1[1], c2[1], t2a0, negv, fah.x);
            clenshaw_step(c1[2], c2[2], t2b0, negv, fb.x);
            clenshaw_step(c1[3], c2[3], t2b0, negv, fbh.x);
            clenshaw_step(c1[4], c2[4], t2a1, negv, fa.x);
            clenshaw_step(c1[5], c2[5], t2a1, negv, fah.x);
            clenshaw_step(c1[6], c2[6], t2b1, negv, fb.x);
            clenshaw_step(c1[7], c2[7], t2b1, negv, fbh.x);
        }
        float tot0 = clenshaw_fin(c1[0], c2[0], fklo, ba0, ca0, sa0)
                   + clenshaw_fin(c1[1], c2[1], fkhi, ba0, ca0, sa0)
                   + clenshaw_fin(c1[2], c2[2], fklo, bb0, cb0, sb0)
                   + clenshaw_fin(c1[3], c2[3], fkhi, bb0, cb0, sb0);
        atomicAdd(out + m0, tot0);
        if (has1) {
            float tot1 = clenshaw_fin(c1[4], c2[4], fklo, ba1, ca1, sa1)
                       + clenshaw_fin(c1[5], c2[5], fkhi, ba1, ca1, sa1)
                       + clenshaw_fin(c1[6], c2[6], fklo, bb1, cb1, sb1)
                       + clenshaw_fin(c1[7], c2[7], fkhi, bb1, cb1, sb1);
            atomicAdd(out + m1, tot1);
        }
    } else if (p0 < P) {   // odd-P tail: single slice, two m
        float ba0 = g_B[(size_t)p0 * M + m0];
        float ba1 = has1 ? g_B[(size_t)p0 * M + m1] : 0.f;
        float sa0, ca0, sa1, ca1;
        __sincosf(TWO_PI_F * ba0, &sa0, &ca0);
        __sincosf(TWO_PI_F * ba1, &sa1, &ca1);
        u64p t2a0 = pk2(2.f * ca0, 2.f * ca0);
        u64p t2a1 = pk2(2.f * ca1, 2.f * ca1);
        u64p c1[4], c2[4];
#pragma unroll
        for (int q = 0; q < 4; q++) { c1[q] = 0ull; c2[q] = 0ull; }
        const ulonglong2* CA = reinterpret_cast<const ulonglong2*>(g_CS + (size_t)p0 * KPAD);
        for (int it = L - 1; it >= 0; it--) {
            ulonglong2 fa  = __ldg(CA + idx0 + it);
            ulonglong2 fah = __ldg(CA + idx0 + L + it);
            clenshaw_step(c1[0], c2[0], t2a0, negv, fa.y);
            clenshaw_step(c1[1], c2[1], t2a0, negv, fah.y);
            clenshaw_step(c1[2], c2[2], t2a1, negv, fa.y);
            clenshaw_step(c1[3], c2[3], t2a1, negv, fah.y);
            clenshaw_step(c1[0], c2[0], t2a0, negv, fa.x);
            clenshaw_step(c1[1], c2[1], t2a0, negv, fah.x);
            clenshaw_step(c1[2], c2[2], t2a1, negv, fa.x);
            clenshaw_step(c1[3], c2[3], t2a1, negv, fah.x);
        }
        float tot0 = clenshaw_fin(c1[0], c2[0], fklo, ba0, ca0, sa0)
                   + clenshaw_fin(c1[1], c2[1], fkhi, ba0, ca0, sa0);
        atomicAdd(out + m0, tot0);
        if (has1) {
            float tot1 = clenshaw_fin(c1[2], c2[2], fklo, ba1, ca1, sa1)
                       + clenshaw_fin(c1[3], c2[3], fkhi, ba1, ca1, sa1);
            atomicAdd(out + m1, tot1);
        }
    }
}

extern "C" void kernel_launch(void* const* d_in, const int* in_sizes, int n_in,
                              void* d_out, int out_size) {
    const float* x     = (const float*)d_in[0];
    const float* y     = (const float*)d_in[1];
    const float* w     = (const float*)d_in[2];
    const float* scale = (const float*)d_in[3];
    const float* xis   = (const float*)d_in[4];
    float* out = (float*)d_out;

    int N = in_sizes[2];
    int d = in_sizes[0] / N;
    int M = out_size;
    int P = in_sizes[4] / d;

    int nb = (N + M + 255) / 256;
    norm_kft_kernel<<<nb, 256>>>(x, y, scale, out, N, M, d, (float)d, P);
    int nmax = (N > M) ? N : M;
    dim3 pgrid((nmax + PROJ_PTS - 1) / PROJ_PTS, 2, 2);
    proj5_kernel<<<pgrid, 256>>>(x, y, xis, N, M, P);
    adjoint_kernel<<<dim3(P, AZ), ABLK>>>(w, N);
    int Mh = (M + 1) / 2;
    int ngroups = (P + PG - 1) / PG;
    forward_kernel<<<dim3((Mh + FBLK - 1) / FBLK, ngroups), FBLK>>>(out, M, P);
}

// round 14
// speedup vs baseline: 1.0651x; 1.0193x over previous
#include <cuda_runtime.h>
#include <math.h>

#define TWO_PI_F  6.28318530717958647692f
#define TWO_PI2_F 19.739208802178716f   /* 2*pi^2 */

#define NMAX 8192
#define PMAX 64
#define KPAD 520
#define ACH 16             /* k per adjoint chunk (multiple of 4!) */
#define AZ 16              /* adjoint N-splits */
#define AE 8               /* elements per adjoint thread */
#define ABLK 64            /* adjoint block size */
#define PROJ_PTS 128
#define PG 2               /* slices per forward block */
#define FBLK 128           /* forward block size */

typedef unsigned long long u64p;

// ---------- packed f32x2 helpers ----------
__device__ __forceinline__ u64p pk2(float lo, float hi) {
    u64p r; asm("mov.b64 %0, {%1, %2};" : "=l"(r) : "f"(lo), "f"(hi)); return r;
}
__device__ __forceinline__ void upk2(u64p v, float& lo, float& hi) {
    asm("mov.b64 {%0, %1}, %2;" : "=f"(lo), "=f"(hi) : "l"(v));
}
__device__ __forceinline__ u64p fma2(u64p a, u64p b, u64p c) {
    u64p d; asm("fma.rn.f32x2 %0, %1, %2, %3;" : "=l"(d) : "l"(a), "l"(b), "l"(c)); return d;
}

// ---------- device scratch ----------
__device__ float  g_A[PMAX * NMAX];    // sf * <x_n, xi_p>, [p][n]
__device__ float  g_B[PMAX * NMAX];    // sf * <y_m, xi_p>, [p][m]
__device__ float2 g_CS[PMAX * KPAD];   // (C*kft2, S*kft2), slot j = k-1
__device__ float  g_kft2[KPAD];        // 2*kft(h)/P, thresholded
__device__ unsigned int g_norm2max_bits;   // reset by last block each call
__device__ unsigned int g_ctr;             // reset by last block each call
__device__ int    g_hmax;
__device__ int    g_kmin;
__device__ float  g_sf;

// ---------- fused: zero buffers + row-norm max + kft (last-block pattern) ----------
// 2 threads per row (halves combined via shfl_xor) -> 2x grid parallelism.
__global__ void __launch_bounds__(256) norm_kft_kernel(
        const float* __restrict__ x, const float* __restrict__ y,
        const float* __restrict__ scale, float* __restrict__ out,
        int N, int M, int d, float dd, int P) {
    __shared__ float wmax[8];
    __shared__ float sred[256];
    __shared__ int s_flag, s_hmax, s_kmin;
    int tid = threadIdx.x;
    int i = blockIdx.x * 256 + tid;
    int stride = gridDim.x * 256;

    float2 z2 = make_float2(0.f, 0.f);
    for (int j = i; j < PMAX * KPAD; j += stride) g_CS[j] = z2;
    for (int j = i; j < M; j += stride) out[j] = 0.f;

    // half-row norms: thread pair (2r, 2r+1) covers row r
    float v = 0.f;
    int T = N + M;
    {
        int row = i >> 1;
        int half = i & 1;
        if (row < T) {
            const float* rp = (row < N) ? (x + (size_t)row * d) : (y + (size_t)(row - N) * d);
            rp += half * (d >> 1);
            float s = 0.f;
            for (int j = 0; j < (d >> 1); j += 4) {
                float4 q = *reinterpret_cast<const float4*>(rp + j);
                s = fmaf(q.x, q.x, s); s = fmaf(q.y, q.y, s);
                s = fmaf(q.z, q.z, s); s = fmaf(q.w, q.w, s);
            }
            v = s;
        }
        v = v + __shfl_xor_sync(0xffffffffu, v, 1);   // full row norm^2 on both lanes
    }
#pragma unroll
    for (int off = 16; off > 1; off >>= 1)
        v = fmaxf(v, __shfl_xor_sync(0xffffffffu, v, off));
    if ((tid & 31) == 0) wmax[tid >> 5] = v;
    __syncthreads();
    if (tid == 0) {
        float m = wmax[0];
#pragma unroll
        for (int wq = 1; wq < 8; wq++) m = fmaxf(m, wmax[wq]);
        if (m > 0.f) atomicMax(&g_norm2max_bits, __float_as_uint(m));
        __threadfence();
        unsigned int prev = atomicAdd(&g_ctr, 1u);
        s_flag = (prev == gridDim.x - 1) ? 1 : 0;
    }
    __syncthreads();
    if (!s_flag) return;

    __threadfence();
    unsigned int nb_bits = atomicAdd(&g_norm2max_bits, 0u);
    float nm = sqrtf(__uint_as_float(nb_bits));
    float sf = 0.3f / nm;
    float sr = scale[0] * sf;
    float s2 = sr * sr;
    float base = 0.5f * dd * __logf(TWO_PI2_F * s2) - lgammaf(0.5f * dd);

    int h1 = tid + 1;
    int h2 = tid + 257;
    float k1 = 0.f, k2 = 0.f;
    {
        float hp = (float)h1;
        float lv = base + (dd - 1.f) * __logf(hp) - TWO_PI2_F * s2 * hp * hp;
        k1 = __expf(lv);
    }
    if (h2 <= 511) {
        float hp = (float)h2;
        float lv = base + (dd - 1.f) * __logf(hp) - TWO_PI2_F * s2 * hp * hp;
        k2 = __expf(lv);
    }
    sred[tid] = fmaxf(k1, k2);
    if (tid == 0) { s_hmax = 0; s_kmin = 0x7fffffff; }
    __syncthreads();
    for (int s = 128; s > 0; s >>= 1) {
        if (tid < s) sred[tid] = fmaxf(sred[tid], sred[tid + s]);
        __syncthreads();
    }
    float maxv = sred[0];
    float thr = maxv * 1e-5f;
    float fscale = 2.f / (float)P;

    bool keep1 = (maxv > 0.f) && (k1 > thr);
    g_kft2[h1] = keep1 ? k1 * fscale : 0.f;
    if (keep1) { atomicMax(&s_hmax, h1); atomicMin(&s_kmin, h1); }
    if (h2 <= 511) {
        bool keep2 = (maxv > 0.f) && (k2 > thr);
        g_kft2[h2] = keep2 ? k2 * fscale : 0.f;
        if (keep2) { atomicMax(&s_hmax, h2); atomicMin(&s_kmin, h2); }
    }
    __syncthreads();
    if (tid == 0) {
        g_kft2[0] = 0.f;
        g_hmax = s_hmax;
        g_kmin = s_kmin;
        g_sf = sf;
        g_ctr = 0u;
        g_norm2max_bits = 0u;
    }
}

// ---------- proj5: smem-staged, P split in halves across blockIdx.z ----------
__global__ void __launch_bounds__(256) proj5_kernel(const float* __restrict__ xpts,
                                                    const float* __restrict__ ypts,
                                                    const float* __restrict__ xis,
                                                    int N, int M, int P) {
    __shared__ float xi_t[64 * 34];
    __shared__ float pts_s[PROJ_PTS * 68];
    int tid = threadIdx.x;
    int which = blockIdx.y;
    int pbase = blockIdx.z * 32;
    const float* pts = which ? ypts : xpts;
    int npts = which ? M : N;
    int base = blockIdx.x * PROJ_PTS;

    for (int idx = tid; idx < 32 * 64; idx += 256) {
        int pl = idx >> 6, dc = idx & 63;
        int pg = pbase + pl;
        xi_t[dc * 34 + pl] = (pg < P) ? xis[(size_t)pg * 64 + dc] : 0.f;
    }
    for (int idx = tid; idx < PROJ_PTS * 16; idx += 256) {
        int r = idx >> 4, j4 = idx & 15;
        int n = base + r;
        float4 v = make_float4(0.f, 0.f, 0.f, 0.f);
        if (n < npts) v = *reinterpret_cast<const float4*>(pts + (size_t)n * 64 + j4 * 4);
        *reinterpret_cast<float4*>(pts_s + r * 68 + j4 * 4) = v;
    }
    __syncthreads();

    int slot = tid & 63;
    int g = tid >> 6;
    const float4* r0 = reinterpret_cast<const float4*>(pts_s + slot * 68);
    const float4* r1 = reinterpret_cast<const float4*>(pts_s + (slot + 64) * 68);

    u64p acc0[4], acc1[4];
#pragma unroll
    for (int q = 0; q < 4; q++) { acc0[q] = 0ull; acc1[q] = 0ull; }

#pragma unroll
    for (int j4 = 0; j4 < 16; j4++) {
        float4 v0 = r0[j4];
        float4 v1 = r1[j4];
#pragma unroll
        for (int s = 0; s < 4; s++) {
            float f0 = (s == 0) ? v0.x : (s == 1) ? v0.y : (s == 2) ? v0.z : v0.w;
            float f1 = (s == 0) ? v1.x : (s == 1) ? v1.y : (s == 2) ? v1.z : v1.w;
            u64p vv0 = pk2(f0, f0);
            u64p vv1 = pk2(f1, f1);
            const float* xb = xi_t + (j4 * 4 + s) * 34 + g * 8;
#pragma unroll
            for (int q = 0; q < 4; q++) {
                u64p xq = *reinterpret_cast<const u64p*>(xb + 2 * q);
                acc0[q] = fma2(vv0, xq, acc0[q]);
                acc1[q] = fma2(vv1, xq, acc1[q]);
            }
        }
    }

    float sf = g_sf;
    float* dst = which ? g_B : g_A;
    int n0 = base + slot, n1 = n0 + 64;
#pragma unroll
    for (int q = 0; q < 4; q++) {
        float a, b, c, dq;
        upk2(acc0[q], a, b);
        upk2(acc1[q], c, dq);
        int p0 = pbase + g * 8 + 2 * q;
        if (p0 < P) {
            if (n0 < npts) dst[(size_t)p0 * npts + n0] = a * sf;
            if (n1 < npts) dst[(size_t)p0 * npts + n1] = c * sf;
        }
        if (p0 + 1 < P) {
            if (n0 < npts) dst[(size_t)(p0 + 1) * npts + n0] = b * sf;
            if (n1 < npts) dst[(size_t)(p0 + 1) * npts + n1] = dq * sf;
        }
    }
}

// ---------- adjoint: chunk-carried Chebyshev + warp reduce-scatter, AE=8, block=64 ----------
__global__ void __launch_bounds__(ABLK) adjoint_kernel(const float* __restrict__ w, int N) {
    int p = blockIdx.x;
    int z = blockIdx.y;
    int hmax = g_hmax;
    if (hmax < 1) return;
    int klo = g_kmin; if (klo < 1) klo = 1;
    int nchunk = (hmax - klo + ACH) / ACH;

    int tid = threadIdx.x;
    int lane = tid & 31;
    const float* arow = g_A + (size_t)p * N;
    int seg = (N + AZ - 1) / AZ;
    int st = z * seg;
    int en = st + seg; if (en > N) en = N;

    float fklo = (float)klo;
    u64p vc[AE], vp[AE], t2p[AE], nt2p[AE], wp[AE];
#pragma unroll
    for (int e = 0; e < AE; e++) {
        int n = st + tid + e * ABLK;
        bool ok = (n < en);
        float a  = ok ? arow[n] : 0.f;
        float ww = ok ? w[n]    : 0.f;
        float us, uc;
        __sincosf(TWO_PI_F * a, &us, &uc);
        float t = fklo * a;
        float er = fmaf(fklo, a, -t);
        float f = (t - rintf(t)) + er;
        float zs, zc;
        __sincosf(TWO_PI_F * f, &zs, &zc);
        float zmc = fmaf(zc, uc,  zs * us);
        float zms = fmaf(zs, uc, -zc * us);
        vc[e] = pk2(zc, zs);
        vp[e] = pk2(-zmc, -zms);
        t2p[e]  = pk2( 2.f * uc,  2.f * uc);
        nt2p[e] = pk2(-2.f * uc, -2.f * uc);
        wp[e] = pk2(ww, ww);
    }

    for (int c = 0; c < nchunk; c++) {
        int k0 = klo + c * ACH;
        u64p accv[ACH];
#pragma unroll
        for (int j = 0; j < ACH; j++) accv[j] = 0ull;

#pragma unroll
        for (int j = 0; j < ACH; j++) {
#pragma unroll
            for (int e = 0; e < AE; e++) {
                accv[j] = fma2(wp[e], vc[e], accv[j]);
                u64p vn = fma2((j & 1) ? nt2p[e] : t2p[e], vc[e], vp[e]);
                vp[e] = vc[e]; vc[e] = vn;
            }
        }

        float a[2 * ACH];
#pragma unroll
        for (int j = 0; j < ACH; j++) upk2(accv[j], a[2 * j], a[2 * j + 1]);

#pragma unroll
        for (int B = 16; B >= 1; B >>= 1) {
            bool bit = (lane & B) != 0;
#pragma unroll
            for (int i = 0; i < B; i++) {
                float snd = bit ? a[i] : a[i + B];
                float kp  = bit ? a[i + B] : a[i];
                a[i] = kp + __shfl_xor_sync(0xffffffffu, snd, B);
            }
        }

        int j = lane >> 1;
        int k = k0 + j;
        float sg = ((j & 2) == 0) ? 1.f : -1.f;
        if (k <= 511) {
            float fkt = g_kft2[k];
            if (fkt != 0.f)
                atomicAdd(reinterpret_cast<float*>(g_CS + (size_t)p * KPAD + (k - 1)) + (lane & 1),
                          a[0] * (sg * fkt));
        }
    }
}

// ---------- forward helpers ----------
__device__ __forceinline__ void clenshaw_step(u64p& b1, u64p& b2, u64p t2, u64p negv, u64p coef) {
    u64p t = fma2(t2, b1, coef);
    u64p n = fma2(negv, b2, t);
    b2 = b1; b1 = n;
}
__device__ __forceinline__ float clenshaw_fin(u64p b1, u64p b2, float fk0,
                                              float bv, float cu, float su) {
    float t = fk0 * bv;
    float e = fmaf(fk0, bv, -t);
    float f = (t - rintf(t)) + e;
    float sK, cK;
    __sincosf(TWO_PI_F * f, &sK, &cK);
    float cKm = fmaf(cK, cu,  sK * su);
    float sKm = fmaf(sK, cu, -cK * su);
    float b1l, b1h, b2l, b2h;
    upk2(b1, b1l, b1h); upk2(b2, b2l, b2h);
    return fmaf(b1l, cK, -b2l * cKm) + fmaf(b1h, sK, -b2h * sKm);
}

// ---------- forward: MV=2 full-range Clenshaw (4 chains, 4 finalizations) ----------
__global__ void __launch_bounds__(FBLK) forward_kernel(float* __restrict__ out,
                                                       int M, int P) {
    int hmax = g_hmax;
    if (hmax < 1) return;
    int kmin = g_kmin; if (kmin < 1) kmin = 1;
    int KE  = ((hmax + 1) >> 1) << 1;
    int jlo = ((kmin - 1) >> 1) << 1;
    int Tp = (KE - jlo) >> 1;       // coefficient pair iterations
    int idx0 = jlo >> 1;
    float fklo = (float)(jlo + 1);
    const u64p negv = pk2(-1.f, -1.f);

    int Mh = (M + 1) >> 1;
    int i = blockIdx.x * FBLK + threadIdx.x;
    if (i >= Mh) return;
    int m0 = i, m1 = i + Mh;
    bool has1 = (m1 < M);
    int p0 = blockIdx.y * PG;

    if (p0 + 1 < P) {
        float ba0 = g_B[(size_t)p0 * M + m0];
        float bb0 = g_B[(size_t)(p0 + 1) * M + m0];
        float ba1 = has1 ? g_B[(size_t)p0 * M + m1] : 0.f;
        float bb1 = has1 ? g_B[(size_t)(p0 + 1) * M + m1] : 0.f;
        float sa0, ca0, sb0, cb0, sa1, ca1, sb1, cb1;
        __sincosf(TWO_PI_F * ba0, &sa0, &ca0);
        __sincosf(TWO_PI_F * bb0, &sb0, &cb0);
        __sincosf(TWO_PI_F * ba1, &sa1, &ca1);
        __sincosf(TWO_PI_F * bb1, &sb1, &cb1);
        u64p t2a0 = pk2(2.f * ca0, 2.f * ca0);
        u64p t2b0 = pk2(2.f * cb0, 2.f * cb0);
        u64p t2a1 = pk2(2.f * ca1, 2.f * ca1);
        u64p t2b1 = pk2(2.f * cb1, 2.f * cb1);
        u64p c1[4], c2[4];
#pragma unroll
        for (int q = 0; q < 4; q++) { c1[q] = 0ull; c2[q] = 0ull; }
        const ulonglong2* CA = reinterpret_cast<const ulonglong2*>(g_CS + (size_t)p0 * KPAD);
        const ulonglong2* CB = reinterpret_cast<const ulonglong2*>(g_CS + (size_t)(p0 + 1) * KPAD);
#pragma unroll 2
        for (int it = Tp - 1; it >= 0; it--) {
            ulonglong2 fa = __ldg(CA + idx0 + it);
            ulonglong2 fb = __ldg(CB + idx0 + it);
            clenshaw_step(c1[0], c2[0], t2a0, negv, fa.y);
            clenshaw_step(c1[1], c2[1], t2b0, negv, fb.y);
            clenshaw_step(c1[2], c2[2], t2a1, negv, fa.y);
            clenshaw_step(c1[3], c2[3], t2b1, negv, fb.y);
            clenshaw_step(c1[0], c2[0], t2a0, negv, fa.x);
            clenshaw_step(c1[1], c2[1], t2b0, negv, fb.x);
            clenshaw_step(c1[2], c2[2], t2a1, negv, fa.x);
            clenshaw_step(c1[3], c2[3], t2b1, negv, fb.x);
        }
        float tot0 = clenshaw_fin(c1[0], c2[0], fklo, ba0, ca0, sa0)
                   + clenshaw_fin(c1[1], c2[1], fklo, bb0, cb0, sb0);
        atomicAdd(out + m0, tot0);
        if (has1) {
            float tot1 = clenshaw_fin(c1[2], c2[2], fklo, ba1, ca1, sa1)
                       + clenshaw_fin(c1[3], c2[3], fklo, bb1, cb1, sb1);
            atomicAdd(out + m1, tot1);
        }
    } else if (p0 < P) {   // odd-P tail: single slice, two m
        float ba0 = g_B[(size_t)p0 * M + m0];
        float ba1 = has1 ? g_B[(size_t)p0 * M + m1] : 0.f;
        float sa0, ca0, sa1, ca1;
        __sincosf(TWO_PI_F * ba0, &sa0, &ca0);
        __sincosf(TWO_PI_F * ba1, &sa1, &ca1);
        u64p t2a0 = pk2(2.f * ca0, 2.f * ca0);
        u64p t2a1 = pk2(2.f * ca1, 2.f * ca1);
        u64p c1[2], c2[2];
#pragma unroll
        for (int q = 0; q < 2; q++) { c1[q] = 0ull; c2[q] = 0ull; }
        const ulonglong2* CA = reinterpret_cast<const ulonglong2*>(g_CS + (size_t)p0 * KPAD);
#pragma unroll 2
        for (int it = Tp - 1; it >= 0; it--) {
            ulonglong2 fa = __ldg(CA + idx0 + it);
            clenshaw_step(c1[0], c2[0], t2a0, negv, fa.y);
            clenshaw_step(c1[1], c2[1], t2a1, negv, fa.y);
            clenshaw_step(c1[0], c2[0], t2a0, negv, fa.x);
            clenshaw_step(c1[1], c2[1], t2a1, negv, fa.x);
        }
        atomicAdd(out + m0, clenshaw_fin(c1[0], c2[0], fklo, ba0, ca0, sa0));
        if (has1)
            atomicAdd(out + m1, clenshaw_fin(c1[1], c2[1], fklo, ba1, ca1, sa1));
    }
}

extern "C" void kernel_launch(void* const* d_in, const int* in_sizes, int n_in,
                              void* d_out, int out_size) {
    const float* x     = (const float*)d_in[0];
    const float* y     = (const float*)d_in[1];
    const float* w     = (const float*)d_in[2];
    const float* scale = (const float*)d_in[3];
    const float* xis   = (const float*)d_in[4];
    float* out = (float*)d_out;

    int N = in_sizes[2];
    int d = in_sizes[0] / N;
    int M = out_size;
    int P = in_sizes[4] / d;

    int nb = (2 * (N + M) + 255) / 256;   // 2 threads per row
    norm_kft_kernel<<<nb, 256>>>(x, y, scale, out, N, M, d, (float)d, P);
    int nmax = (N > M) ? N : M;
    dim3 pgrid((nmax + PROJ_PTS - 1) / PROJ_PTS, 2, 2);
    proj5_kernel<<<pgrid, 256>>>(x, y, xis, N, M, P);
    adjoint_kernel<<<dim3(P, AZ), ABLK>>>(w, N);
    int Mh = (M + 1) / 2;
    int ngroups = (P + PG - 1) / PG;
    forward_kernel<<<dim3((Mh + FBLK - 1) / FBLK, ngroups), FBLK>>>(out, M, P);
}

// round 15
// speedup vs baseline: 1.0727x; 1.0072x over previous
#include <cuda_runtime.h>
#include <math.h>

#define TWO_PI_F  6.28318530717958647692f
#define TWO_PI2_F 19.739208802178716f   /* 2*pi^2 */

#define NMAX 8192
#define PMAX 64
#define KPAD 520
#define ACH 16             /* k per adjoint chunk (multiple of 4!) */
#define AZ 16              /* adjoint N-splits */
#define AE 8               /* elements per adjoint thread */
#define ABLK 64            /* adjoint block size */
#define PROJ_PTS 128
#define PG 2               /* slices per forward block */
#define FBLK 128           /* forward block size */
#define MAXPAIRS 260       /* max coefficient pairs (KPAD/2) */

typedef unsigned long long u64p;

// ---------- packed f32x2 helpers ----------
__device__ __forceinline__ u64p pk2(float lo, float hi) {
    u64p r; asm("mov.b64 %0, {%1, %2};" : "=l"(r) : "f"(lo), "f"(hi)); return r;
}
__device__ __forceinline__ void upk2(u64p v, float& lo, float& hi) {
    asm("mov.b64 {%0, %1}, %2;" : "=f"(lo), "=f"(hi) : "l"(v));
}
__device__ __forceinline__ u64p fma2(u64p a, u64p b, u64p c) {
    u64p d; asm("fma.rn.f32x2 %0, %1, %2, %3;" : "=l"(d) : "l"(a), "l"(b), "l"(c)); return d;
}

// ---------- device scratch ----------
__device__ float  g_A[PMAX * NMAX];    // sf * <x_n, xi_p>, [p][n]
__device__ float  g_B[PMAX * NMAX];    // sf * <y_m, xi_p>, [p][m]
__device__ float2 g_CS[PMAX * KPAD];   // (C*kft2, S*kft2), slot j = k-1
__device__ float  g_kft2[KPAD];        // 2*kft(h)/P, thresholded
__device__ unsigned int g_norm2max_bits;   // reset by last block each call
__device__ unsigned int g_ctr;             // reset by last block each call
__device__ int    g_hmax;
__device__ int    g_kmin;
__device__ float  g_sf;

// ---------- fused: zero buffers + row-norm max + kft (last-block pattern) ----------
__global__ void __launch_bounds__(256) norm_kft_kernel(
        const float* __restrict__ x, const float* __restrict__ y,
        const float* __restrict__ scale, float* __restrict__ out,
        int N, int M, int d, float dd, int P) {
    __shared__ float wmax[8];
    __shared__ float sred[256];
    __shared__ int s_flag, s_hmax, s_kmin;
    int tid = threadIdx.x;
    int i = blockIdx.x * 256 + tid;
    int stride = gridDim.x * 256;

    float2 z2 = make_float2(0.f, 0.f);
    for (int j = i; j < PMAX * KPAD; j += stride) g_CS[j] = z2;
    for (int j = i; j < M; j += stride) out[j] = 0.f;

    // half-row norms: thread pair (2r, 2r+1) covers row r
    float v = 0.f;
    int T = N + M;
    {
        int row = i >> 1;
        int half = i & 1;
        if (row < T) {
            const float* rp = (row < N) ? (x + (size_t)row * d) : (y + (size_t)(row - N) * d);
            rp += half * (d >> 1);
            float s = 0.f;
            for (int j = 0; j < (d >> 1); j += 4) {
                float4 q = *reinterpret_cast<const float4*>(rp + j);
                s = fmaf(q.x, q.x, s); s = fmaf(q.y, q.y, s);
                s = fmaf(q.z, q.z, s); s = fmaf(q.w, q.w, s);
            }
            v = s;
        }
        v = v + __shfl_xor_sync(0xffffffffu, v, 1);
    }
#pragma unroll
    for (int off = 16; off > 1; off >>= 1)
        v = fmaxf(v, __shfl_xor_sync(0xffffffffu, v, off));
    if ((tid & 31) == 0) wmax[tid >> 5] = v;
    __syncthreads();
    if (tid == 0) {
        float m = wmax[0];
#pragma unroll
        for (int wq = 1; wq < 8; wq++) m = fmaxf(m, wmax[wq]);
        if (m > 0.f) atomicMax(&g_norm2max_bits, __float_as_uint(m));
        __threadfence();
        unsigned int prev = atomicAdd(&g_ctr, 1u);
        s_flag = (prev == gridDim.x - 1) ? 1 : 0;
    }
    __syncthreads();
    if (!s_flag) return;

    __threadfence();
    unsigned int nb_bits = atomicAdd(&g_norm2max_bits, 0u);
    float nm = sqrtf(__uint_as_float(nb_bits));
    float sf = 0.3f / nm;
    float sr = scale[0] * sf;
    float s2 = sr * sr;
    float base = 0.5f * dd * __logf(TWO_PI2_F * s2) - lgammaf(0.5f * dd);

    int h1 = tid + 1;
    int h2 = tid + 257;
    float k1 = 0.f, k2 = 0.f;
    {
        float hp = (float)h1;
        float lv = base + (dd - 1.f) * __logf(hp) - TWO_PI2_F * s2 * hp * hp;
        k1 = __expf(lv);
    }
    if (h2 <= 511) {
        float hp = (float)h2;
        float lv = base + (dd - 1.f) * __logf(hp) - TWO_PI2_F * s2 * hp * hp;
        k2 = __expf(lv);
    }
    sred[tid] = fmaxf(k1, k2);
    if (tid == 0) { s_hmax = 0; s_kmin = 0x7fffffff; }
    __syncthreads();
    for (int s = 128; s > 0; s >>= 1) {
        if (tid < s) sred[tid] = fmaxf(sred[tid], sred[tid + s]);
        __syncthreads();
    }
    float maxv = sred[0];
    float thr = maxv * 1e-5f;
    float fscale = 2.f / (float)P;

    bool keep1 = (maxv > 0.f) && (k1 > thr);
    g_kft2[h1] = keep1 ? k1 * fscale : 0.f;
    if (keep1) { atomicMax(&s_hmax, h1); atomicMin(&s_kmin, h1); }
    if (h2 <= 511) {
        bool keep2 = (maxv > 0.f) && (k2 > thr);
        g_kft2[h2] = keep2 ? k2 * fscale : 0.f;
        if (keep2) { atomicMax(&s_hmax, h2); atomicMin(&s_kmin, h2); }
    }
    __syncthreads();
    if (tid == 0) {
        g_kft2[0] = 0.f;
        g_hmax = s_hmax;
        g_kmin = s_kmin;
        g_sf = sf;
        g_ctr = 0u;
        g_norm2max_bits = 0u;
    }
}

// ---------- proj5: smem-staged, P split in halves across blockIdx.z ----------
__global__ void __launch_bounds__(256) proj5_kernel(const float* __restrict__ xpts,
                                                    const float* __restrict__ ypts,
                                                    const float* __restrict__ xis,
                                                    int N, int M, int P) {
    __shared__ float xi_t[64 * 34];
    __shared__ float pts_s[PROJ_PTS * 68];
    int tid = threadIdx.x;
    int which = blockIdx.y;
    int pbase = blockIdx.z * 32;
    const float* pts = which ? ypts : xpts;
    int npts = which ? M : N;
    int base = blockIdx.x * PROJ_PTS;

    for (int idx = tid; idx < 32 * 64; idx += 256) {
        int pl = idx >> 6, dc = idx & 63;
        int pg = pbase + pl;
        xi_t[dc * 34 + pl] = (pg < P) ? xis[(size_t)pg * 64 + dc] : 0.f;
    }
    for (int idx = tid; idx < PROJ_PTS * 16; idx += 256) {
        int r = idx >> 4, j4 = idx & 15;
        int n = base + r;
        float4 v = make_float4(0.f, 0.f, 0.f, 0.f);
        if (n < npts) v = *reinterpret_cast<const float4*>(pts + (size_t)n * 64 + j4 * 4);
        *reinterpret_cast<float4*>(pts_s + r * 68 + j4 * 4) = v;
    }
    __syncthreads();

    int slot = tid & 63;
    int g = tid >> 6;
    const float4* r0 = reinterpret_cast<const float4*>(pts_s + slot * 68);
    const float4* r1 = reinterpret_cast<const float4*>(pts_s + (slot + 64) * 68);

    u64p acc0[4], acc1[4];
#pragma unroll
    for (int q = 0; q < 4; q++) { acc0[q] = 0ull; acc1[q] = 0ull; }

#pragma unroll
    for (int j4 = 0; j4 < 16; j4++) {
        float4 v0 = r0[j4];
        float4 v1 = r1[j4];
#pragma unroll
        for (int s = 0; s < 4; s++) {
            float f0 = (s == 0) ? v0.x : (s == 1) ? v0.y : (s == 2) ? v0.z : v0.w;
            float f1 = (s == 0) ? v1.x : (s == 1) ? v1.y : (s == 2) ? v1.z : v1.w;
            u64p vv0 = pk2(f0, f0);
            u64p vv1 = pk2(f1, f1);
            const float* xb = xi_t + (j4 * 4 + s) * 34 + g * 8;
#pragma unroll
            for (int q = 0; q < 4; q++) {
                u64p xq = *reinterpret_cast<const u64p*>(xb + 2 * q);
                acc0[q] = fma2(vv0, xq, acc0[q]);
                acc1[q] = fma2(vv1, xq, acc1[q]);
            }
        }
    }

    float sf = g_sf;
    float* dst = which ? g_B : g_A;
    int n0 = base + slot, n1 = n0 + 64;
#pragma unroll
    for (int q = 0; q < 4; q++) {
        float a, b, c, dq;
        upk2(acc0[q], a, b);
        upk2(acc1[q], c, dq);
        int p0 = pbase + g * 8 + 2 * q;
        if (p0 < P) {
            if (n0 < npts) dst[(size_t)p0 * npts + n0] = a * sf;
            if (n1 < npts) dst[(size_t)p0 * npts + n1] = c * sf;
        }
        if (p0 + 1 < P) {
            if (n0 < npts) dst[(size_t)(p0 + 1) * npts + n0] = b * sf;
            if (n1 < npts) dst[(size_t)(p0 + 1) * npts + n1] = dq * sf;
        }
    }
}

// ---------- adjoint: chunk-carried Chebyshev + warp reduce-scatter, AE=8, block=64 ----------
__global__ void __launch_bounds__(ABLK) adjoint_kernel(const float* __restrict__ w, int N) {
    int p = blockIdx.x;
    int z = blockIdx.y;
    int hmax = g_hmax;
    if (hmax < 1) return;
    int klo = g_kmin; if (klo < 1) klo = 1;
    int nchunk = (hmax - klo + ACH) / ACH;

    int tid = threadIdx.x;
    int lane = tid & 31;
    const float* arow = g_A + (size_t)p * N;
    int seg = (N + AZ - 1) / AZ;
    int st = z * seg;
    int en = st + seg; if (en > N) en = N;

    float fklo = (float)klo;
    u64p vc[AE], vp[AE], t2p[AE], nt2p[AE], wp[AE];
#pragma unroll
    for (int e = 0; e < AE; e++) {
        int n = st + tid + e * ABLK;
        bool ok = (n < en);
        float a  = ok ? arow[n] : 0.f;
        float ww = ok ? w[n]    : 0.f;
        float us, uc;
        __sincosf(TWO_PI_F * a, &us, &uc);
        float t = fklo * a;
        float er = fmaf(fklo, a, -t);
        float f = (t - rintf(t)) + er;
        float zs, zc;
        __sincosf(TWO_PI_F * f, &zs, &zc);
        float zmc = fmaf(zc, uc,  zs * us);
        float zms = fmaf(zs, uc, -zc * us);
        vc[e] = pk2(zc, zs);
        vp[e] = pk2(-zmc, -zms);
        t2p[e]  = pk2( 2.f * uc,  2.f * uc);
        nt2p[e] = pk2(-2.f * uc, -2.f * uc);
        wp[e] = pk2(ww, ww);
    }

    for (int c = 0; c < nchunk; c++) {
        int k0 = klo + c * ACH;
        u64p accv[ACH];
#pragma unroll
        for (int j = 0; j < ACH; j++) accv[j] = 0ull;

#pragma unroll
        for (int j = 0; j < ACH; j++) {
#pragma unroll
            for (int e = 0; e < AE; e++) {
                accv[j] = fma2(wp[e], vc[e], accv[j]);
                u64p vn = fma2((j & 1) ? nt2p[e] : t2p[e], vc[e], vp[e]);
                vp[e] = vc[e]; vc[e] = vn;
            }
        }

        float a[2 * ACH];
#pragma unroll
        for (int j = 0; j < ACH; j++) upk2(accv[j], a[2 * j], a[2 * j + 1]);

#pragma unroll
        for (int B = 16; B >= 1; B >>= 1) {
            bool bit = (lane & B) != 0;
#pragma unroll
            for (int i = 0; i < B; i++) {
                float snd = bit ? a[i] : a[i + B];
                float kp  = bit ? a[i + B] : a[i];
                a[i] = kp + __shfl_xor_sync(0xffffffffu, snd, B);
            }
        }

        int j = lane >> 1;
        int k = k0 + j;
        float sg = ((j & 2) == 0) ? 1.f : -1.f;
        if (k <= 511) {
            float fkt = g_kft2[k];
            if (fkt != 0.f)
                atomicAdd(reinterpret_cast<float*>(g_CS + (size_t)p * KPAD + (k - 1)) + (lane & 1),
                          a[0] * (sg * fkt));
        }
    }
}

// ---------- forward helpers ----------
__device__ __forceinline__ void clenshaw_step(u64p& b1, u64p& b2, u64p t2, u64p negv, u64p coef) {
    u64p t = fma2(t2, b1, coef);
    u64p n = fma2(negv, b2, t);
    b2 = b1; b1 = n;
}
__device__ __forceinline__ float clenshaw_fin(u64p b1, u64p b2, float fk0,
                                              float bv, float cu, float su) {
    float t = fk0 * bv;
    float e = fmaf(fk0, bv, -t);
    float f = (t - rintf(t)) + e;
    float sK, cK;
    __sincosf(TWO_PI_F * f, &sK, &cK);
    float cKm = fmaf(cK, cu,  sK * su);
    float sKm = fmaf(sK, cu, -cK * su);
    float b1l, b1h, b2l, b2h;
    upk2(b1, b1l, b1h); upk2(b2, b2l, b2h);
    return fmaf(b1l, cK, -b2l * cKm) + fmaf(b1h, sK, -b2h * sKm);
}

// ---------- forward: MV=2 Clenshaw, coefficients staged in SMEM ----------
// One L2 round-trip per coefficient per BLOCK (staged via coalesced LDG.128),
// loop reads uniform-address LDS.128 broadcasts -> no exposed L2 latency.
__global__ void __launch_bounds__(FBLK) forward_kernel(float* __restrict__ out,
                                                       int M, int P) {
    __shared__ ulonglong2 sA[MAXPAIRS];
    __shared__ ulonglong2 sB[MAXPAIRS];
    int hmax = g_hmax;
    if (hmax < 1) return;
    int kmin = g_kmin; if (kmin < 1) kmin = 1;
    int KE  = ((hmax + 1) >> 1) << 1;
    int jlo = ((kmin - 1) >> 1) << 1;
    int Tp = (KE - jlo) >> 1;       // coefficient pair iterations
    int idx0 = jlo >> 1;
    float fklo = (float)(jlo + 1);
    const u64p negv = pk2(-1.f, -1.f);

    int tid = threadIdx.x;
    int p0 = blockIdx.y * PG;
    bool twop = (p0 + 1 < P);
    {
        const ulonglong2* CA = reinterpret_cast<const ulonglong2*>(g_CS + (size_t)p0 * KPAD);
        const ulonglong2* CB = twop
            ? reinterpret_cast<const ulonglong2*>(g_CS + (size_t)(p0 + 1) * KPAD) : CA;
        for (int t = tid; t < Tp; t += FBLK) {
            sA[t] = __ldg(CA + idx0 + t);
            sB[t] = __ldg(CB + idx0 + t);
        }
    }
    __syncthreads();

    int Mh = (M + 1) >> 1;
    int i = blockIdx.x * FBLK + tid;
    if (i >= Mh) return;
    int m0 = i, m1 = i + Mh;
    bool has1 = (m1 < M);

    if (twop) {
        float ba0 = g_B[(size_t)p0 * M + m0];
        float bb0 = g_B[(size_t)(p0 + 1) * M + m0];
        float ba1 = has1 ? g_B[(size_t)p0 * M + m1] : 0.f;
        float bb1 = has1 ? g_B[(size_t)(p0 + 1) * M + m1] : 0.f;
        float sa0, ca0, sb0, cb0, sa1, ca1, sb1, cb1;
        __sincosf(TWO_PI_F * ba0, &sa0, &ca0);
        __sincosf(TWO_PI_F * bb0, &sb0, &cb0);
        __sincosf(TWO_PI_F * ba1, &sa1, &ca1);
        __sincosf(TWO_PI_F * bb1, &sb1, &cb1);
        u64p t2a0 = pk2(2.f * ca0, 2.f * ca0);
        u64p t2b0 = pk2(2.f * cb0, 2.f * cb0);
        u64p t2a1 = pk2(2.f * ca1, 2.f * ca1);
        u64p t2b1 = pk2(2.f * cb1, 2.f * cb1);
        u64p c1[4], c2[4];
#pragma unroll
        for (int q = 0; q < 4; q++) { c1[q] = 0ull; c2[q] = 0ull; }
#pragma unroll 2
        for (int it = Tp - 1; it >= 0; it--) {
            ulonglong2 fa = sA[it];
            ulonglong2 fb = sB[it];
            clenshaw_step(c1[0], c2[0], t2a0, negv, fa.y);
            clenshaw_step(c1[1], c2[1], t2b0, negv, fb.y);
            clenshaw_step(c1[2], c2[2], t2a1, negv, fa.y);
            clenshaw_step(c1[3], c2[3], t2b1, negv, fb.y);
            clenshaw_step(c1[0], c2[0], t2a0, negv, fa.x);
            clenshaw_step(c1[1], c2[1], t2b0, negv, fb.x);
            clenshaw_step(c1[2], c2[2], t2a1, negv, fa.x);
            clenshaw_step(c1[3], c2[3], t2b1, negv, fb.x);
        }
        float tot0 = clenshaw_fin(c1[0], c2[0], fklo, ba0, ca0, sa0)
                   + clenshaw_fin(c1[1], c2[1], fklo, bb0, cb0, sb0);
        atomicAdd(out + m0, tot0);
        if (has1) {
            float tot1 = clenshaw_fin(c1[2], c2[2], fklo, ba1, ca1, sa1)
                       + clenshaw_fin(c1[3], c2[3], fklo, bb1, cb1, sb1);
            atomicAdd(out + m1, tot1);
        }
    } else {   // odd-P tail: single slice, two m
        float ba0 = g_B[(size_t)p0 * M + m0];
        float ba1 = has1 ? g_B[(size_t)p0 * M + m1] : 0.f;
        float sa0, ca0, sa1, ca1;
        __sincosf(TWO_PI_F * ba0, &sa0, &ca0);
        __sincosf(TWO_PI_F * ba1, &sa1, &ca1);
        u64p t2a0 = pk2(2.f * ca0, 2.f * ca0);
        u64p t2a1 = pk2(2.f * ca1, 2.f * ca1);
        u64p c1[2], c2[2];
#pragma unroll
        for (int q = 0; q < 2; q++) { c1[q] = 0ull; c2[q] = 0ull; }
#pragma unroll 2
        for (int it = Tp - 1; it >= 0; it--) {
            ulonglong2 fa = sA[it];
            clenshaw_step(c1[0], c2[0], t2a0, negv, fa.y);
            clenshaw_step(c1[1], c2[1], t2a1, negv, fa.y);
            clenshaw_step(c1[0], c2[0], t2a0, negv, fa.x);
            clenshaw_step(c1[1], c2[1], t2a1, negv, fa.x);
        }
        atomicAdd(out + m0, clenshaw_fin(c1[0], c2[0], fklo, ba0, ca0, sa0));
        if (has1)
            atomicAdd(out + m1, clenshaw_fin(c1[1], c2[1], fklo, ba1, ca1, sa1));
    }
}

extern "C" void kernel_launch(void* const* d_in, const int* in_sizes, int n_in,
                              void* d_out, int out_size) {
    const float* x     = (const float*)d_in[0];
    const float* y     = (const float*)d_in[1];
    const float* w     = (const float*)d_in[2];
    const float* scale = (const float*)d_in[3];
    const float* xis   = (const float*)d_in[4];
    float* out = (float*)d_out;

    int N = in_sizes[2];
    int d = in_sizes[0] / N;
    int M = out_size;
    int P = in_sizes[4] / d;

    int nb = (2 * (N + M) + 255) / 256;   // 2 threads per row
    norm_kft_kernel<<<nb, 256>>>(x, y, scale, out, N, M, d, (float)d, P);
    int nmax = (N > M) ? N : M;
    dim3 pgrid((nmax + PROJ_PTS - 1) / PROJ_PTS, 2, 2);
    proj5_kernel<<<pgrid, 256>>>(x, y, xis, N, M, P);
    adjoint_kernel<<<dim3(P, AZ), ABLK>>>(w, N);
    int Mh = (M + 1) / 2;
    int ngroups = (P + PG - 1) / PG;
    forward_kernel<<<dim3((Mh + FBLK - 1) / FBLK, ngroups), FBLK>>>(out, M, P);
}

// round 16
// speedup vs baseline: 1.0738x; 1.0010x over previous
#include <cuda_runtime.h>
#include <math.h>

#define TWO_PI_F  6.28318530717958647692f
#define TWO_PI2_F 19.739208802178716f   /* 2*pi^2 */

#define NMAX 8192
#define PMAX 64
#define KPAD 520
#define ACH 16             /* k per adjoint chunk (multiple of 4!) */
#define AZ 16              /* adjoint N-splits */
#define AE 8               /* elements per adjoint thread */
#define ABLK 64            /* adjoint block size */
#define PROJ_PTS 128
#define PG 2               /* slices per forward block */
#define FBLK 128           /* forward block size */
#define MV 4               /* m-values per forward thread */
#define MAXPAIRS 260       /* max coefficient pairs (KPAD/2) */

typedef unsigned long long u64p;

// ---------- packed f32x2 helpers ----------
__device__ __forceinline__ u64p pk2(float lo, float hi) {
    u64p r; asm("mov.b64 %0, {%1, %2};" : "=l"(r) : "f"(lo), "f"(hi)); return r;
}
__device__ __forceinline__ void upk2(u64p v, float& lo, float& hi) {
    asm("mov.b64 {%0, %1}, %2;" : "=f"(lo), "=f"(hi) : "l"(v));
}
__device__ __forceinline__ u64p fma2(u64p a, u64p b, u64p c) {
    u64p d; asm("fma.rn.f32x2 %0, %1, %2, %3;" : "=l"(d) : "l"(a), "l"(b), "l"(c)); return d;
}

// ---------- device scratch ----------
__device__ float  g_A[PMAX * NMAX];    // sf * <x_n, xi_p>, [p][n]
__device__ float  g_B[PMAX * NMAX];    // sf * <y_m, xi_p>, [p][m]
__device__ float2 g_CS[PMAX * KPAD];   // (C*kft2, S*kft2), slot j = k-1
__device__ float  g_kft2[KPAD];        // 2*kft(h)/P, thresholded
__device__ unsigned int g_norm2max_bits;   // reset by last block each call
__device__ unsigned int g_ctr;             // reset by last block each call
__device__ int    g_hmax;
__device__ int    g_kmin;
__device__ float  g_sf;

// ---------- fused: zero buffers + row-norm max + kft (last-block pattern) ----------
__global__ void __launch_bounds__(256) norm_kft_kernel(
        const float* __restrict__ x, const float* __restrict__ y,
        const float* __restrict__ scale, float* __restrict__ out,
        int N, int M, int d, float dd, int P) {
    __shared__ float wmax[8];
    __shared__ float sred[256];
    __shared__ int s_flag, s_hmax, s_kmin;
    int tid = threadIdx.x;
    int i = blockIdx.x * 256 + tid;
    int stride = gridDim.x * 256;

    float2 z2 = make_float2(0.f, 0.f);
    for (int j = i; j < PMAX * KPAD; j += stride) g_CS[j] = z2;
    for (int j = i; j < M; j += stride) out[j] = 0.f;

    // half-row norms: thread pair (2r, 2r+1) covers row r
    float v = 0.f;
    int T = N + M;
    {
        int row = i >> 1;
        int half = i & 1;
        if (row < T) {
            const float* rp = (row < N) ? (x + (size_t)row * d) : (y + (size_t)(row - N) * d);
            rp += half * (d >> 1);
            float s = 0.f;
            for (int j = 0; j < (d >> 1); j += 4) {
                float4 q = *reinterpret_cast<const float4*>(rp + j);
                s = fmaf(q.x, q.x, s); s = fmaf(q.y, q.y, s);
                s = fmaf(q.z, q.z, s); s = fmaf(q.w, q.w, s);
            }
            v = s;
        }
        v = v + __shfl_xor_sync(0xffffffffu, v, 1);
    }
#pragma unroll
    for (int off = 16; off > 1; off >>= 1)
        v = fmaxf(v, __shfl_xor_sync(0xffffffffu, v, off));
    if ((tid & 31) == 0) wmax[tid >> 5] = v;
    __syncthreads();
    if (tid == 0) {
        float m = wmax[0];
#pragma unroll
        for (int wq = 1; wq < 8; wq++) m = fmaxf(m, wmax[wq]);
        if (m > 0.f) atomicMax(&g_norm2max_bits, __float_as_uint(m));
        __threadfence();
        unsigned int prev = atomicAdd(&g_ctr, 1u);
        s_flag = (prev == gridDim.x - 1) ? 1 : 0;
    }
    __syncthreads();
    if (!s_flag) return;

    __threadfence();
    unsigned int nb_bits = atomicAdd(&g_norm2max_bits, 0u);
    float nm = sqrtf(__uint_as_float(nb_bits));
    float sf = 0.3f / nm;
    float sr = scale[0] * sf;
    float s2 = sr * sr;
    float base = 0.5f * dd * __logf(TWO_PI2_F * s2) - lgammaf(0.5f * dd);

    int h1 = tid + 1;
    int h2 = tid + 257;
    float k1 = 0.f, k2 = 0.f;
    {
        float hp = (float)h1;
        float lv = base + (dd - 1.f) * __logf(hp) - TWO_PI2_F * s2 * hp * hp;
        k1 = __expf(lv);
    }
    if (h2 <= 511) {
        float hp = (float)h2;
        float lv = base + (dd - 1.f) * __logf(hp) - TWO_PI2_F * s2 * hp * hp;
        k2 = __expf(lv);
    }
    sred[tid] = fmaxf(k1, k2);
    if (tid == 0) { s_hmax = 0; s_kmin = 0x7fffffff; }
    __syncthreads();
    for (int s = 128; s > 0; s >>= 1) {
        if (tid < s) sred[tid] = fmaxf(sred[tid], sred[tid + s]);
        __syncthreads();
    }
    float maxv = sred[0];
    float thr = maxv * 1e-5f;
    float fscale = 2.f / (float)P;

    bool keep1 = (maxv > 0.f) && (k1 > thr);
    g_kft2[h1] = keep1 ? k1 * fscale : 0.f;
    if (keep1) { atomicMax(&s_hmax, h1); atomicMin(&s_kmin, h1); }
    if (h2 <= 511) {
        bool keep2 = (maxv > 0.f) && (k2 > thr);
        g_kft2[h2] = keep2 ? k2 * fscale : 0.f;
        if (keep2) { atomicMax(&s_hmax, h2); atomicMin(&s_kmin, h2); }
    }
    __syncthreads();
    if (tid == 0) {
        g_kft2[0] = 0.f;
        g_hmax = s_hmax;
        g_kmin = s_kmin;
        g_sf = sf;
        g_ctr = 0u;
        g_norm2max_bits = 0u;
    }
}

// ---------- proj5: smem-staged, P split in halves across blockIdx.z ----------
__global__ void __launch_bounds__(256) proj5_kernel(const float* __restrict__ xpts,
                                                    const float* __restrict__ ypts,
                                                    const float* __restrict__ xis,
                                                    int N, int M, int P) {
    __shared__ float xi_t[64 * 34];
    __shared__ float pts_s[PROJ_PTS * 68];
    int tid = threadIdx.x;
    int which = blockIdx.y;
    int pbase = blockIdx.z * 32;
    const float* pts = which ? ypts : xpts;
    int npts = which ? M : N;
    int base = blockIdx.x * PROJ_PTS;

    for (int idx = tid; idx < 32 * 64; idx += 256) {
        int pl = idx >> 6, dc = idx & 63;
        int pg = pbase + pl;
        xi_t[dc * 34 + pl] = (pg < P) ? xis[(size_t)pg * 64 + dc] : 0.f;
    }
    for (int idx = tid; idx < PROJ_PTS * 16; idx += 256) {
        int r = idx >> 4, j4 = idx & 15;
        int n = base + r;
        float4 v = make_float4(0.f, 0.f, 0.f, 0.f);
        if (n < npts) v = *reinterpret_cast<const float4*>(pts + (size_t)n * 64 + j4 * 4);
        *reinterpret_cast<float4*>(pts_s + r * 68 + j4 * 4) = v;
    }
    __syncthreads();

    int slot = tid & 63;
    int g = tid >> 6;
    const float4* r0 = reinterpret_cast<const float4*>(pts_s + slot * 68);
    const float4* r1 = reinterpret_cast<const float4*>(pts_s + (slot + 64) * 68);

    u64p acc0[4], acc1[4];
#pragma unroll
    for (int q = 0; q < 4; q++) { acc0[q] = 0ull; acc1[q] = 0ull; }

#pragma unroll
    for (int j4 = 0; j4 < 16; j4++) {
        float4 v0 = r0[j4];
        float4 v1 = r1[j4];
#pragma unroll
        for (int s = 0; s < 4; s++) {
            float f0 = (s == 0) ? v0.x : (s == 1) ? v0.y : (s == 2) ? v0.z : v0.w;
            float f1 = (s == 0) ? v1.x : (s == 1) ? v1.y : (s == 2) ? v1.z : v1.w;
            u64p vv0 = pk2(f0, f0);
            u64p vv1 = pk2(f1, f1);
            const float* xb = xi_t + (j4 * 4 + s) * 34 + g * 8;
#pragma unroll
            for (int q = 0; q < 4; q++) {
                u64p xq = *reinterpret_cast<const u64p*>(xb + 2 * q);
                acc0[q] = fma2(vv0, xq, acc0[q]);
                acc1[q] = fma2(vv1, xq, acc1[q]);
            }
        }
    }

    float sf = g_sf;
    float* dst = which ? g_B : g_A;
    int n0 = base + slot, n1 = n0 + 64;
#pragma unroll
    for (int q = 0; q < 4; q++) {
        float a, b, c, dq;
        upk2(acc0[q], a, b);
        upk2(acc1[q], c, dq);
        int p0 = pbase + g * 8 + 2 * q;
        if (p0 < P) {
            if (n0 < npts) dst[(size_t)p0 * npts + n0] = a * sf;
            if (n1 < npts) dst[(size_t)p0 * npts + n1] = c * sf;
        }
        if (p0 + 1 < P) {
            if (n0 < npts) dst[(size_t)(p0 + 1) * npts + n0] = b * sf;
            if (n1 < npts) dst[(size_t)(p0 + 1) * npts + n1] = dq * sf;
        }
    }
}

// ---------- adjoint: chunk-carried Chebyshev + warp reduce-scatter, AE=8, block=64 ----------
__global__ void __launch_bounds__(ABLK) adjoint_kernel(const float* __restrict__ w, int N) {
    int p = blockIdx.x;
    int z = blockIdx.y;
    int hmax = g_hmax;
    if (hmax < 1) return;
    int klo = g_kmin; if (klo < 1) klo = 1;
    int nchunk = (hmax - klo + ACH) / ACH;

    int tid = threadIdx.x;
    int lane = tid & 31;
    const float* arow = g_A + (size_t)p * N;
    int seg = (N + AZ - 1) / AZ;
    int st = z * seg;
    int en = st + seg; if (en > N) en = N;

    float fklo = (float)klo;
    u64p vc[AE], vp[AE], t2p[AE], nt2p[AE], wp[AE];
#pragma unroll
    for (int e = 0; e < AE; e++) {
        int n = st + tid + e * ABLK;
        bool ok = (n < en);
        float a  = ok ? arow[n] : 0.f;
        float ww = ok ? w[n]    : 0.f;
        float us, uc;
        __sincosf(TWO_PI_F * a, &us, &uc);
        float t = fklo * a;
        float er = fmaf(fklo, a, -t);
        float f = (t - rintf(t)) + er;
        float zs, zc;
        __sincosf(TWO_PI_F * f, &zs, &zc);
        float zmc = fmaf(zc, uc,  zs * us);
        float zms = fmaf(zs, uc, -zc * us);
        vc[e] = pk2(zc, zs);
        vp[e] = pk2(-zmc, -zms);
        t2p[e]  = pk2( 2.f * uc,  2.f * uc);
        nt2p[e] = pk2(-2.f * uc, -2.f * uc);
        wp[e] = pk2(ww, ww);
    }

    for (int c = 0; c < nchunk; c++) {
        int k0 = klo + c * ACH;
        u64p accv[ACH];
#pragma unroll
        for (int j = 0; j < ACH; j++) accv[j] = 0ull;

#pragma unroll
        for (int j = 0; j < ACH; j++) {
#pragma unroll
            for (int e = 0; e < AE; e++) {
                accv[j] = fma2(wp[e], vc[e], accv[j]);
                u64p vn = fma2((j & 1) ? nt2p[e] : t2p[e], vc[e], vp[e]);
                vp[e] = vc[e]; vc[e] = vn;
            }
        }

        float a[2 * ACH];
#pragma unroll
        for (int j = 0; j < ACH; j++) upk2(accv[j], a[2 * j], a[2 * j + 1]);

#pragma unroll
        for (int B = 16; B >= 1; B >>= 1) {
            bool bit = (lane & B) != 0;
#pragma unroll
            for (int i = 0; i < B; i++) {
                float snd = bit ? a[i] : a[i + B];
                float kp  = bit ? a[i + B] : a[i];
                a[i] = kp + __shfl_xor_sync(0xffffffffu, snd, B);
            }
        }

        int j = lane >> 1;
        int k = k0 + j;
        float sg = ((j & 2) == 0) ? 1.f : -1.f;
        if (k <= 511) {
            float fkt = g_kft2[k];
            if (fkt != 0.f)
                atomicAdd(reinterpret_cast<float*>(g_CS + (size_t)p * KPAD + (k - 1)) + (lane & 1),
                          a[0] * (sg * fkt));
        }
    }
}

// ---------- forward helpers ----------
__device__ __forceinline__ void clenshaw_step(u64p& b1, u64p& b2, u64p t2, u64p negv, u64p coef) {
    u64p t = fma2(t2, b1, coef);
    u64p n = fma2(negv, b2, t);
    b2 = b1; b1 = n;
}
__device__ __forceinline__ float clenshaw_fin(u64p b1, u64p b2, float fk0,
                                              float bv, float cu, float su) {
    float t = fk0 * bv;
    float e = fmaf(fk0, bv, -t);
    float f = (t - rintf(t)) + e;
    float sK, cK;
    __sincosf(TWO_PI_F * f, &sK, &cK);
    float cKm = fmaf(cK, cu,  sK * su);
    float sKm = fmaf(sK, cu, -cK * su);
    float b1l, b1h, b2l, b2h;
    upk2(b1, b1l, b1h); upk2(b2, b2l, b2h);
    return fmaf(b1l, cK, -b2l * cKm) + fmaf(b1h, sK, -b2h * sKm);
}

// ---------- forward: MV=4 x PG=2 Clenshaw (8 chains), coefficients in SMEM ----------
// 32 essential fma2 per iteration amortize 2 LDS + loop overhead; warp count
// halves vs MV=2 so prologue/finalization cost halves too.
__global__ void __launch_bounds__(FBLK) forward_kernel(float* __restrict__ out,
                                                       int M, int P) {
    __shared__ ulonglong2 sA[MAXPAIRS];
    __shared__ ulonglong2 sB[MAXPAIRS];
    int hmax = g_hmax;
    if (hmax < 1) return;
    int kmin = g_kmin; if (kmin < 1) kmin = 1;
    int KE  = ((hmax + 1) >> 1) << 1;
    int jlo = ((kmin - 1) >> 1) << 1;
    int Tp = (KE - jlo) >> 1;       // coefficient pair iterations
    int idx0 = jlo >> 1;
    float fklo = (float)(jlo + 1);
    const u64p negv = pk2(-1.f, -1.f);

    int tid = threadIdx.x;
    int p0 = blockIdx.y * PG;
    bool twop = (p0 + 1 < P);
    {
        const ulonglong2* CA = reinterpret_cast<const ulonglong2*>(g_CS + (size_t)p0 * KPAD);
        const ulonglong2* CB = twop
            ? reinterpret_cast<const ulonglong2*>(g_CS + (size_t)(p0 + 1) * KPAD) : CA;
        for (int t = tid; t < Tp; t += FBLK) {
            sA[t] = __ldg(CA + idx0 + t);
            sB[t] = __ldg(CB + idx0 + t);
        }
    }
    __syncthreads();

    int Mq = (M + MV - 1) / MV;
    int i = blockIdx.x * FBLK + tid;
    if (i >= Mq) return;

    int   mm[MV];
    bool  ok[MV];
    float bA[MV], sA_[MV], cA_[MV];   // slice p0 angles per m
    float bB[MV], sB_[MV], cB_[MV];   // slice p0+1 angles per m
    u64p  t2A[MV], t2B[MV];
#pragma unroll
    for (int q = 0; q < MV; q++) {
        mm[q] = i + q * Mq;
        ok[q] = (mm[q] < M);
        int midx = ok[q] ? mm[q] : 0;
        bA[q] = g_B[(size_t)p0 * M + midx];
        bB[q] = twop ? g_B[(size_t)(p0 + 1) * M + midx] : 0.f;
        __sincosf(TWO_PI_F * bA[q], &sA_[q], &cA_[q]);
        __sincosf(TWO_PI_F * bB[q], &sB_[q], &cB_[q]);
        t2A[q] = pk2(2.f * cA_[q], 2.f * cA_[q]);
        t2B[q] = pk2(2.f * cB_[q], 2.f * cB_[q]);
    }

    u64p c1a[MV], c2a[MV], c1b[MV], c2b[MV];
#pragma unroll
    for (int q = 0; q < MV; q++) { c1a[q] = 0ull; c2a[q] = 0ull; c1b[q] = 0ull; c2b[q] = 0ull; }

    if (twop) {
        for (int it = Tp - 1; it >= 0; it--) {
            ulonglong2 fa = sA[it];
            ulonglong2 fb = sB[it];
#pragma unroll
            for (int q = 0; q < MV; q++) {
                clenshaw_step(c1a[q], c2a[q], t2A[q], negv, fa.y);
                clenshaw_step(c1b[q], c2b[q], t2B[q], negv, fb.y);
            }
#pragma unroll
            for (int q = 0; q < MV; q++) {
                clenshaw_step(c1a[q], c2a[q], t2A[q], negv, fa.x);
                clenshaw_step(c1b[q], c2b[q], t2B[q], negv, fb.x);
            }
        }
#pragma unroll
        for (int q = 0; q < MV; q++) {
            if (!ok[q]) continue;
            float tot = clenshaw_fin(c1a[q], c2a[q], fklo, bA[q], cA_[q], sA_[q])
                      + clenshaw_fin(c1b[q], c2b[q], fklo, bB[q], cB_[q], sB_[q]);
            atomicAdd(out + mm[q], tot);
        }
    } else {   // odd-P tail: single slice
        for (int it = Tp - 1; it >= 0; it--) {
            ulonglong2 fa = sA[it];
#pragma unroll
            for (int q = 0; q < MV; q++)
                clenshaw_step(c1a[q], c2a[q], t2A[q], negv, fa.y);
#pragma unroll
            for (int q = 0; q < MV; q++)
                clenshaw_step(c1a[q], c2a[q], t2A[q], negv, fa.x);
        }
#pragma unroll
        for (int q = 0; q < MV; q++) {
            if (!ok[q]) continue;
            atomicAdd(out + mm[q],
                      clenshaw_fin(c1a[q], c2a[q], fklo, bA[q], cA_[q], sA_[q]));
        }
    }
}

extern "C" void kernel_launch(void* const* d_in, const int* in_sizes, int n_in,
                              void* d_out, int out_size) {
    const float* x     = (const float*)d_in[0];
    const float* y     = (const float*)d_in[1];
    const float* w     = (const float*)d_in[2];
    const float* scale = (const float*)d_in[3];
    const float* xis   = (const float*)d_in[4];
    float* out = (float*)d_out;

    int N = in_sizes[2];
    int d = in_sizes[0] / N;
    int M = out_size;
    int P = in_sizes[4] / d;

    int nb = (2 * (N + M) + 255) / 256;   // 2 threads per row
    norm_kft_kernel<<<nb, 256>>>(x, y, scale, out, N, M, d, (float)d, P);
    int nmax = (N > M) ? N : M;
    dim3 pgrid((nmax + PROJ_PTS - 1) / PROJ_PTS, 2, 2);
    proj5_kernel<<<pgrid, 256>>>(x, y, xis, N, M, P);
    adjoint_kernel<<<dim3(P, AZ), ABLK>>>(w, N);
    int Mq = (M + MV - 1) / MV;
    int ngroups = (P + PG - 1) / PG;
    forward_kernel<<<dim3((Mq + FBLK - 1) / FBLK, ngroups), FBLK>>>(out, M, P);
}